// round 11
// baseline (speedup 1.0000x reference)
#include <cuda_runtime.h>
#include <cuda_bf16.h>
#include <cstdint>

// ---------------------------------------------------------------------------
// AttentionBlock: out = X + softmax_axis1(causal(Q K^T))/sqrt(k) @ V
// B=8, T=2048, D=1024. bf16 mma.sync GEMMs. 3 CTAs/SM, 64B-row smem (no
// swizzle needed), softmax fused into GEMM2 epilogue, norm folded into V.
// ---------------------------------------------------------------------------

#define BATCH 8
#define TT    2048
#define DD    1024

#define BM 128
#define BN 128
#define BKH 32                          // bf16 k-elems per stage (64 B rows)
#define NST 3
#define TILE_B  8192                    // 128 rows x 64 bytes
#define STAGE_B (2 * TILE_B)            // 16384
#define SMEM_BYTES (NST * STAGE_B)      // 49152

// ---------------- scratch (device globals; no allocation allowed) ----------
__device__ __nv_bfloat16 g_Xb[(size_t)16384 * 1024];
__device__ __nv_bfloat16 g_Wt[(size_t)3072 * 1024];        // [n][k] = W[k][n]
__device__ float         g_biasc[3072];
__device__ __nv_bfloat16 g_QKV[(size_t)16384 * 3072];      // [b*T + t][3072]
__device__ __nv_bfloat16 g_probs[(size_t)BATCH * TT * TT]; // p~ = exp(logit)
__device__ __nv_bfloat16 g_Vt[(size_t)BATCH * DD * TT];    // [b][v][t] * inv[t]
__device__ float         g_psum[BATCH * TT];

// ---------------- helpers ----------------------------------------------------
__device__ __forceinline__ void cp16(uint32_t s, const void* g) {
    asm volatile("cp.async.cg.shared.global [%0], [%1], 16;" :: "r"(s), "l"(g));
}
__device__ __forceinline__ void ldsm_x4(uint32_t* r, uint32_t saddr) {
    asm volatile("ldmatrix.sync.aligned.m8n8.x4.shared.b16 {%0,%1,%2,%3}, [%4];"
        : "=r"(r[0]), "=r"(r[1]), "=r"(r[2]), "=r"(r[3]) : "r"(saddr));
}
__device__ __forceinline__ void mma16816(float* d, const uint32_t* a,
                                         uint32_t b0, uint32_t b1) {
    asm volatile(
        "mma.sync.aligned.m16n8k16.row.col.f32.bf16.bf16.f32 "
        "{%0,%1,%2,%3},{%4,%5,%6,%7},{%8,%9},{%0,%1,%2,%3};\n"
        : "+f"(d[0]), "+f"(d[1]), "+f"(d[2]), "+f"(d[3])
        : "r"(a[0]), "r"(a[1]), "r"(a[2]), "r"(a[3]), "r"(b0), "r"(b1));
}

// ---------------- bf16 GEMM: C[m][n] = sum_k A[m][k]*B[n][k] ------------------
// CTA 128x128, 128 threads, 4 warps (2x2), warp tile 64x64, 3 CTAs/SM.
// MODE 0: out bf16 += bias[n]                              (QKV projection)
// MODE 1: out bf16 = causal(exp(acc)); column sums -> psum (logits/probs);
//         tiles strictly above diagonal return (never read downstream).
// MODE 2: out fp32 += Res; k-loop truncated at tileM+BM; y reversed so the
//         longest tiles launch first (wave packing).                   (AV)
template<int MODE>
__global__ void __launch_bounds__(128, 3)
gemm_bf16(const __nv_bfloat16* __restrict__ A, const __nv_bfloat16* __restrict__ B,
          void* __restrict__ Cv,
          const float* __restrict__ bias, const float* __restrict__ Res,
          float* __restrict__ psum,
          int lda, int ldb, int ldc, int K,
          long long sAb, long long sBb, long long sCb, long long sRb)
{
    extern __shared__ __align__(1024) char smem[];
    const int tid = threadIdx.x;
    const int bz  = blockIdx.z;
    const int by  = (MODE == 2) ? (gridDim.y - 1 - blockIdx.y) : blockIdx.y;
    const int tileM = by * BM;
    const int tileN = blockIdx.x * BN;

    if (MODE == 1 && tileN >= tileM + BM) return;   // never read by GEMM3

    A += (size_t)bz * sAb;
    B += (size_t)bz * sBb;
    if (MODE == 2) Res += (size_t)bz * sRb;

    const int wid = tid >> 5, lane = tid & 31;
    const int g = lane >> 2, t4 = lane & 3;
    const int wm = (wid >> 1) * 64;
    const int wn = (wid & 1) * 64;

    const int lj = lane >> 3, lr = lane & 7;
    const int mrow = (lj & 1) * 8 + lr;     // row within 16-row tile
    const int klo  = (lj >> 1) * 16;        // byte offset within k16 step

    float acc[4][8][4];
    #pragma unroll
    for (int i = 0; i < 4; i++)
        #pragma unroll
        for (int j = 0; j < 8; j++)
            #pragma unroll
            for (int k = 0; k < 4; k++) acc[i][j][k] = 0.f;

    const uint32_t smem_u = (uint32_t)__cvta_generic_to_shared(smem);

    // per-thread fill addressing: thread handles rows (tid>>2)+{0,32,64,96},
    // 16B chunk (tid&3) within the 64B row.
    const int frow = tid >> 2, fc = tid & 3;
    const __nv_bfloat16* gA = A + (size_t)(tileM + frow) * lda + fc * 8;
    const __nv_bfloat16* gB = B + (size_t)(tileN + frow) * ldb + fc * 8;
    const uint32_t sOff = (uint32_t)(frow * 64 + fc * 16);

    auto fill = [&](int s) {
        const uint32_t base = smem_u + (s % NST) * STAGE_B + sOff;
        const int kk = s * BKH;
        #pragma unroll
        for (int i = 0; i < 4; i++)
            cp16(base + i * 32 * 64, gA + (size_t)i * 32 * lda + kk);
        #pragma unroll
        for (int i = 0; i < 4; i++)
            cp16(base + TILE_B + i * 32 * 64, gB + (size_t)i * 32 * ldb + kk);
    };

    const int Keff = (MODE == 2) ? (tileM + BM) : K;
    const int KT = Keff / BKH;                       // >= 4

    fill(0);
    asm volatile("cp.async.commit_group;");
    fill(1);
    asm volatile("cp.async.commit_group;");

    for (int s = 0; s < KT; s++) {
        if (s < KT - 1) asm volatile("cp.async.wait_group 1;");
        else            asm volatile("cp.async.wait_group 0;");
        __syncthreads();

        if (s + 2 < KT) {
            fill(s + 2);
            asm volatile("cp.async.commit_group;");
        }

        const uint32_t stg = smem_u + (uint32_t)((s % NST) * STAGE_B);
        const uint32_t aBase = stg + (uint32_t)((wm + mrow) * 64 + klo);
        const uint32_t bBase = stg + TILE_B + (uint32_t)((wn + mrow) * 64 + klo);

        #pragma unroll
        for (int ks = 0; ks < 2; ks++) {            // 2 k16-steps per stage
            const uint32_t kb = (uint32_t)(ks * 32);
            uint32_t qf[4][4];
            ldsm_x4(qf[0], bBase + 0 * 16 * 64 + kb);
            ldsm_x4(qf[1], bBase + 1 * 16 * 64 + kb);
            ldsm_x4(qf[2], bBase + 2 * 16 * 64 + kb);
            ldsm_x4(qf[3], bBase + 3 * 16 * 64 + kb);
            uint32_t af[2][4];
            ldsm_x4(af[0], aBase + kb);
            #pragma unroll
            for (int mt = 0; mt < 4; mt++) {
                const int cur = mt & 1;
                if (mt < 3)
                    ldsm_x4(af[cur ^ 1], aBase + (mt + 1) * 16 * 64 + kb);
                #pragma unroll
                for (int np = 0; np < 4; np++)
                    #pragma unroll
                    for (int h = 0; h < 2; h++)
                        mma16816(acc[mt][np * 2 + h], af[cur],
                                 qf[np][h], qf[np][h + 2]);
            }
        }
    }

    // ---------------- epilogues ----------------
    if (MODE == 0) {
        __nv_bfloat16* C = (__nv_bfloat16*)Cv + (size_t)bz * sCb;
        #pragma unroll
        for (int mt = 0; mt < 4; mt++)
            #pragma unroll
            for (int nt = 0; nt < 8; nt++) {
                int r   = tileM + wm + mt * 16 + g;
                int col = tileN + wn + nt * 8 + 2 * t4;
                float2 bb = *(const float2*)(bias + col);
                float2 v0 = make_float2(acc[mt][nt][0] + bb.x, acc[mt][nt][1] + bb.y);
                float2 v1 = make_float2(acc[mt][nt][2] + bb.x, acc[mt][nt][3] + bb.y);
                *(__nv_bfloat162*)(C + (size_t)r * ldc + col) =
                    __float22bfloat162_rn(v0);
                *(__nv_bfloat162*)(C + (size_t)(r + 8) * ldc + col) =
                    __float22bfloat162_rn(v1);
            }
    } else if (MODE == 1) {
        __nv_bfloat16* C = (__nv_bfloat16*)Cv + (size_t)bz * sCb;
        float cs[8][2];
        #pragma unroll
        for (int nt = 0; nt < 8; nt++) { cs[nt][0] = 0.f; cs[nt][1] = 0.f; }
        #pragma unroll
        for (int mt = 0; mt < 4; mt++)
            #pragma unroll
            for (int nt = 0; nt < 8; nt++) {
                int r0 = tileM + wm + mt * 16 + g;
                int c0 = tileN + wn + nt * 8 + 2 * t4;
                float e00 = (r0     >= c0    ) ? __expf(acc[mt][nt][0]) : 0.f;
                float e01 = (r0     >= c0 + 1) ? __expf(acc[mt][nt][1]) : 0.f;
                float e10 = (r0 + 8 >= c0    ) ? __expf(acc[mt][nt][2]) : 0.f;
                float e11 = (r0 + 8 >= c0 + 1) ? __expf(acc[mt][nt][3]) : 0.f;
                *(__nv_bfloat162*)(C + (size_t)r0 * ldc + c0) =
                    __float22bfloat162_rn(make_float2(e00, e01));
                *(__nv_bfloat162*)(C + (size_t)(r0 + 8) * ldc + c0) =
                    __float22bfloat162_rn(make_float2(e10, e11));
                cs[nt][0] += e00 + e10;
                cs[nt][1] += e01 + e11;
            }
        #pragma unroll
        for (int nt = 0; nt < 8; nt++)
            #pragma unroll
            for (int h = 0; h < 2; h++) {
                float v = cs[nt][h];
                v += __shfl_xor_sync(0xffffffffu, v, 4);
                v += __shfl_xor_sync(0xffffffffu, v, 8);
                v += __shfl_xor_sync(0xffffffffu, v, 16);
                if (lane < 4)
                    atomicAdd(psum + bz * TT + tileN + wn + nt * 8 + 2 * t4 + h, v);
            }
    } else {
        float* C = (float*)Cv + (size_t)bz * sCb;
        #pragma unroll
        for (int mt = 0; mt < 4; mt++)
            #pragma unroll
            for (int nt = 0; nt < 8; nt++) {
                int r   = tileM + wm + mt * 16 + g;
                int col = tileN + wn + nt * 8 + 2 * t4;
                float2 v0 = make_float2(acc[mt][nt][0], acc[mt][nt][1]);
                float2 v1 = make_float2(acc[mt][nt][2], acc[mt][nt][3]);
                float2 r0 = *(const float2*)(Res + (size_t)r * ldc + col);
                float2 r1 = *(const float2*)(Res + (size_t)(r + 8) * ldc + col);
                v0.x += r0.x; v0.y += r0.y;
                v1.x += r1.x; v1.y += r1.y;
                *(float2*)(C + (size_t)r * ldc + col)       = v0;
                *(float2*)(C + (size_t)(r + 8) * ldc + col) = v1;
            }
    }
}

// ---------------- transpose W (3x 1024x1024 fp32) -> Wt[3072][1024] bf16 -----
__global__ void k_transposeW(const float* __restrict__ Wq,
                             const float* __restrict__ Wk,
                             const float* __restrict__ Wv,
                             __nv_bfloat16* __restrict__ Wt)
{
    __shared__ float s[32][33];
    const int nb = blockIdx.x * 32;
    const int kb = blockIdx.y * 32;
    const float* W = (nb < 1024) ? Wq : (nb < 2048 ? Wk : Wv);
    const int nl = nb & 1023;
    const int tx = threadIdx.x, ty = threadIdx.y;
    #pragma unroll
    for (int r = 0; r < 4; r++) {
        int k = kb + ty + r * 8;
        s[ty + r * 8][tx] = W[k * 1024 + nl + tx];
    }
    __syncthreads();
    #pragma unroll
    for (int r = 0; r < 4; r++) {
        int n = nb + ty + r * 8;
        Wt[(size_t)n * 1024 + kb + tx] = __float2bfloat16(s[tx][ty + r * 8]);
    }
}

// ---------------- bias concat + psum zero --------------------------------------
__global__ void k_prep(const float* __restrict__ bq, const float* __restrict__ bk,
                       const float* __restrict__ bv, float* __restrict__ biasc,
                       float* __restrict__ psum)
{
    int i = blockIdx.x * 256 + threadIdx.x;   // 16384
    psum[i] = 0.f;
    if (i < 3072)
        biasc[i] = (i < 1024) ? bq[i] : (i < 2048 ? bk[i - 1024] : bv[i - 2048]);
}

// ---------------- X fp32 -> bf16 ------------------------------------------------
__global__ void k_cvtX(const float4* __restrict__ in, __nv_bfloat162* __restrict__ o)
{
    int i = blockIdx.x * 256 + threadIdx.x;
    float4 v = in[i];
    o[2 * i]     = __float22bfloat162_rn(make_float2(v.x, v.y));
    o[2 * i + 1] = __float22bfloat162_rn(make_float2(v.z, v.w));
}

// ------ transpose V slice of QKV -> Vt[b][v][t], scaled by 1/(32*psum[t]) ------
__global__ void k_transposeVS(const __nv_bfloat16* __restrict__ QKV,
                              const float* __restrict__ psum,
                              __nv_bfloat16* __restrict__ Vt)
{
    __shared__ __nv_bfloat16 s[32][34];
    const int tb = blockIdx.x * 32;
    const int vb = blockIdx.y * 32;
    const int b  = blockIdx.z;
    const int tx = threadIdx.x, ty = threadIdx.y;
    #pragma unroll
    for (int r = 0; r < 4; r++) {
        int t = tb + ty + r * 8;
        s[ty + r * 8][tx] = QKV[((size_t)(b * TT + t)) * 3072 + 2048 + vb + tx];
    }
    __syncthreads();
    float iv = 1.0f / (psum[b * TT + tb + tx] * 32.0f);
    #pragma unroll
    for (int r = 0; r < 4; r++) {
        int v = vb + ty + r * 8;
        Vt[(size_t)b * DD * TT + (size_t)v * TT + tb + tx] =
            __float2bfloat16(__bfloat162float(s[tx][ty + r * 8]) * iv);
    }
}

// ---------------- launch --------------------------------------------------------
extern "C" void kernel_launch(void* const* d_in, const int* in_sizes, int n_in,
                              void* d_out, int out_size)
{
    (void)in_sizes; (void)n_in; (void)out_size;
    const float* X  = (const float*)d_in[0];
    const float* Wq = (const float*)d_in[1];
    const float* bq = (const float*)d_in[2];
    const float* Wk = (const float*)d_in[3];
    const float* bk = (const float*)d_in[4];
    const float* Wv = (const float*)d_in[5];
    const float* bv = (const float*)d_in[6];
    float* out = (float*)d_out;

    __nv_bfloat16 *Xb, *Wt, *QKV, *probs, *Vt;
    float *biasc, *psum;
    cudaGetSymbolAddress((void**)&Xb,    g_Xb);
    cudaGetSymbolAddress((void**)&Wt,    g_Wt);
    cudaGetSymbolAddress((void**)&biasc, g_biasc);
    cudaGetSymbolAddress((void**)&QKV,   g_QKV);
    cudaGetSymbolAddress((void**)&probs, g_probs);
    cudaGetSymbolAddress((void**)&Vt,    g_Vt);
    cudaGetSymbolAddress((void**)&psum,  g_psum);

    cudaFuncSetAttribute(gemm_bf16<0>, cudaFuncAttributeMaxDynamicSharedMemorySize,
                         SMEM_BYTES);
    cudaFuncSetAttribute(gemm_bf16<1>, cudaFuncAttributeMaxDynamicSharedMemorySize,
                         SMEM_BYTES);
    cudaFuncSetAttribute(gemm_bf16<2>, cudaFuncAttributeMaxDynamicSharedMemorySize,
                         SMEM_BYTES);

    // 1) preprocessing
    k_transposeW<<<dim3(96, 32), dim3(32, 8)>>>(Wq, Wk, Wv, Wt);
    k_prep<<<64, 256>>>(bq, bk, bv, biasc, psum);
    k_cvtX<<<16384, 256>>>((const float4*)X, (__nv_bfloat162*)Xb);

    // 2) QKV[16384,3072] = Xb @ Wt^T + biasc  (bf16 out)
    gemm_bf16<0><<<dim3(24, 128, 1), 128, SMEM_BYTES>>>(
        Xb, Wt, QKV, biasc, nullptr, nullptr,
        1024, 1024, 3072, 1024,
        0LL, 0LL, 0LL, 0LL);

    // 3) p~[b] = causal(exp(Q[b] @ K[b]^T)) bf16; column sums -> psum
    gemm_bf16<1><<<dim3(16, 16, 8), 128, SMEM_BYTES>>>(
        QKV, QKV + 1024, probs, nullptr, nullptr, psum,
        3072, 3072, 2048, 1024,
        (long long)TT * 3072, (long long)TT * 3072, (long long)TT * TT, 0LL);

    // 4) V transpose + scale by 1/(32*psum) -> Vt[b][v][t]
    k_transposeVS<<<dim3(64, 32, 8), dim3(32, 8)>>>(QKV, psum, Vt);

    // 5) out[b] = X[b] + p~[b] @ Vt'[b]^T  (causal-truncated K, longest-first)
    gemm_bf16<2><<<dim3(8, 16, 8), 128, SMEM_BYTES>>>(
        probs, Vt, out, nullptr, X, nullptr,
        2048, 2048, 1024, 2048,
        (long long)TT * TT, (long long)DD * TT, (long long)TT * DD,
        (long long)TT * DD);
}

// round 12
// speedup vs baseline: 1.2615x; 1.2615x over previous
#include <cuda_runtime.h>
#include <cuda_bf16.h>
#include <cstdint>

// ---------------------------------------------------------------------------
// AttentionBlock: out = X + softmax_axis1(causal(Q K^T))/sqrt(k) @ V
// B=8, T=2048, D=1024. bf16 mma.sync GEMMs. 3 CTAs/SM, 64B-row smem with SW64
// XOR swizzle (conflict-free for ldmatrix + cp.async), softmax fused into
// GEMM2 epilogue, normalization folded into V.
// ---------------------------------------------------------------------------

#define BATCH 8
#define TT    2048
#define DD    1024

#define BM 128
#define BN 128
#define BKH 32                          // bf16 k-elems per stage (64 B rows)
#define NST 3
#define TILE_B  8192                    // 128 rows x 64 bytes
#define STAGE_B (2 * TILE_B)            // 16384
#define SMEM_BYTES (NST * STAGE_B)      // 49152

// ---------------- scratch (device globals; no allocation allowed) ----------
__device__ __nv_bfloat16 g_Xb[(size_t)16384 * 1024];
__device__ __nv_bfloat16 g_Wt[(size_t)3072 * 1024];        // [n][k] = W[k][n]
__device__ float         g_biasc[3072];
__device__ __nv_bfloat16 g_QKV[(size_t)16384 * 3072];      // [b*T + t][3072]
__device__ __nv_bfloat16 g_probs[(size_t)BATCH * TT * TT]; // p~ = exp(logit)
__device__ __nv_bfloat16 g_Vt[(size_t)BATCH * DD * TT];    // [b][v][t] * inv[t]
__device__ float         g_psum[BATCH * TT];

// ---------------- helpers ----------------------------------------------------
__device__ __forceinline__ void cp16(uint32_t s, const void* g) {
    asm volatile("cp.async.cg.shared.global [%0], [%1], 16;" :: "r"(s), "l"(g));
}
__device__ __forceinline__ void ldsm_x4(uint32_t* r, uint32_t saddr) {
    asm volatile("ldmatrix.sync.aligned.m8n8.x4.shared.b16 {%0,%1,%2,%3}, [%4];"
        : "=r"(r[0]), "=r"(r[1]), "=r"(r[2]), "=r"(r[3]) : "r"(saddr));
}
__device__ __forceinline__ void mma16816(float* d, const uint32_t* a,
                                         uint32_t b0, uint32_t b1) {
    asm volatile(
        "mma.sync.aligned.m16n8k16.row.col.f32.bf16.bf16.f32 "
        "{%0,%1,%2,%3},{%4,%5,%6,%7},{%8,%9},{%0,%1,%2,%3};\n"
        : "+f"(d[0]), "+f"(d[1]), "+f"(d[2]), "+f"(d[3])
        : "r"(a[0]), "r"(a[1]), "r"(a[2]), "r"(a[3]), "r"(b0), "r"(b1));
}

// ---------------- bf16 GEMM: C[m][n] = sum_k A[m][k]*B[n][k] ------------------
// CTA 128x128, 128 threads, 4 warps (2x2), warp tile 64x64, 3 CTAs/SM.
// SW64 swizzle: byte_off ^= (byte_off>>3)&0x30  (key = (row%8)*8 & 0x30).
// MODE 0: out bf16 += bias[n]                              (QKV projection)
// MODE 1: out bf16 = causal(exp(acc)); column sums -> psum (logits/probs);
//         tiles strictly above diagonal return (never read downstream).
// MODE 2: out fp32 += Res; k-loop truncated at tileM+BM; y reversed so the
//         longest tiles launch first (wave packing).                   (AV)
template<int MODE>
__global__ void __launch_bounds__(128, 3)
gemm_bf16(const __nv_bfloat16* __restrict__ A, const __nv_bfloat16* __restrict__ B,
          void* __restrict__ Cv,
          const float* __restrict__ bias, const float* __restrict__ Res,
          float* __restrict__ psum,
          int lda, int ldb, int ldc, int K,
          long long sAb, long long sBb, long long sCb, long long sRb)
{
    extern __shared__ __align__(1024) char smem[];
    const int tid = threadIdx.x;
    const int bz  = blockIdx.z;
    const int by  = (MODE == 2) ? (gridDim.y - 1 - blockIdx.y) : blockIdx.y;
    const int tileM = by * BM;
    const int tileN = blockIdx.x * BN;

    if (MODE == 1 && tileN >= tileM + BM) return;   // never read by GEMM3

    A += (size_t)bz * sAb;
    B += (size_t)bz * sBb;
    if (MODE == 2) Res += (size_t)bz * sRb;

    const int wid = tid >> 5, lane = tid & 31;
    const int g = lane >> 2, t4 = lane & 3;
    const int wm = (wid >> 1) * 64;
    const int wn = (wid & 1) * 64;

    const int lj = lane >> 3, lr = lane & 7;
    const int mrow = (lj & 1) * 8 + lr;     // row within 16-row tile
    const int klo  = (lj >> 1) * 16;        // byte offset within k16 step
    const int swz  = (lr * 8) & 0x30;       // SW64 key, row%8 == lr here

    float acc[4][8][4];
    #pragma unroll
    for (int i = 0; i < 4; i++)
        #pragma unroll
        for (int j = 0; j < 8; j++)
            #pragma unroll
            for (int k = 0; k < 4; k++) acc[i][j][k] = 0.f;

    const uint32_t smem_u = (uint32_t)__cvta_generic_to_shared(smem);

    // fill: thread handles rows (tid>>2)+{0,32,64,96}, 16B chunk (tid&3).
    // SW64 key depends only on row%8 (stable under +32 row steps).
    const int frow = tid >> 2, fc = tid & 3;
    const __nv_bfloat16* gA = A + (size_t)(tileM + frow) * lda + fc * 8;
    const __nv_bfloat16* gB = B + (size_t)(tileN + frow) * ldb + fc * 8;
    const uint32_t sOff = (uint32_t)(frow * 64 + ((fc * 16) ^ ((frow * 8) & 0x30)));

    auto fill = [&](int s) {
        const uint32_t base = smem_u + (s % NST) * STAGE_B + sOff;
        const int kk = s * BKH;
        #pragma unroll
        for (int i = 0; i < 4; i++)
            cp16(base + i * 32 * 64, gA + (size_t)i * 32 * lda + kk);
        #pragma unroll
        for (int i = 0; i < 4; i++)
            cp16(base + TILE_B + i * 32 * 64, gB + (size_t)i * 32 * ldb + kk);
    };

    const int Keff = (MODE == 2) ? (tileM + BM) : K;
    const int KT = Keff / BKH;                       // >= 4

    fill(0);
    asm volatile("cp.async.commit_group;");
    fill(1);
    asm volatile("cp.async.commit_group;");

    for (int s = 0; s < KT; s++) {
        if (s < KT - 1) asm volatile("cp.async.wait_group 1;");
        else            asm volatile("cp.async.wait_group 0;");
        __syncthreads();

        if (s + 2 < KT) {
            fill(s + 2);
            asm volatile("cp.async.commit_group;");
        }

        const uint32_t stg = smem_u + (uint32_t)((s % NST) * STAGE_B);
        const uint32_t aBase = stg + (uint32_t)((wm + mrow) * 64);
        const uint32_t bBase = stg + TILE_B + (uint32_t)((wn + mrow) * 64);

        #pragma unroll
        for (int ks = 0; ks < 2; ks++) {            // 2 k16-steps per stage
            const uint32_t kb = (uint32_t)((ks * 32 + klo) ^ swz);
            uint32_t qf[4][4];
            ldsm_x4(qf[0], bBase + 0 * 16 * 64 + kb);
            ldsm_x4(qf[1], bBase + 1 * 16 * 64 + kb);
            ldsm_x4(qf[2], bBase + 2 * 16 * 64 + kb);
            ldsm_x4(qf[3], bBase + 3 * 16 * 64 + kb);
            uint32_t af[2][4];
            ldsm_x4(af[0], aBase + kb);
            #pragma unroll
            for (int mt = 0; mt < 4; mt++) {
                const int cur = mt & 1;
                if (mt < 3)
                    ldsm_x4(af[cur ^ 1], aBase + (mt + 1) * 16 * 64 + kb);
                #pragma unroll
                for (int np = 0; np < 4; np++)
                    #pragma unroll
                    for (int h = 0; h < 2; h++)
                        mma16816(acc[mt][np * 2 + h], af[cur],
                                 qf[np][h], qf[np][h + 2]);
            }
        }
    }

    // ---------------- epilogues ----------------
    if (MODE == 0) {
        __nv_bfloat16* C = (__nv_bfloat16*)Cv + (size_t)bz * sCb;
        #pragma unroll
        for (int mt = 0; mt < 4; mt++)
            #pragma unroll
            for (int nt = 0; nt < 8; nt++) {
                int r   = tileM + wm + mt * 16 + g;
                int col = tileN + wn + nt * 8 + 2 * t4;
                float2 bb = *(const float2*)(bias + col);
                float2 v0 = make_float2(acc[mt][nt][0] + bb.x, acc[mt][nt][1] + bb.y);
                float2 v1 = make_float2(acc[mt][nt][2] + bb.x, acc[mt][nt][3] + bb.y);
                *(__nv_bfloat162*)(C + (size_t)r * ldc + col) =
                    __float22bfloat162_rn(v0);
                *(__nv_bfloat162*)(C + (size_t)(r + 8) * ldc + col) =
                    __float22bfloat162_rn(v1);
            }
    } else if (MODE == 1) {
        __nv_bfloat16* C = (__nv_bfloat16*)Cv + (size_t)bz * sCb;
        float cs[8][2];
        #pragma unroll
        for (int nt = 0; nt < 8; nt++) { cs[nt][0] = 0.f; cs[nt][1] = 0.f; }
        #pragma unroll
        for (int mt = 0; mt < 4; mt++)
            #pragma unroll
            for (int nt = 0; nt < 8; nt++) {
                int r0 = tileM + wm + mt * 16 + g;
                int c0 = tileN + wn + nt * 8 + 2 * t4;
                float e00 = (r0     >= c0    ) ? __expf(acc[mt][nt][0]) : 0.f;
                float e01 = (r0     >= c0 + 1) ? __expf(acc[mt][nt][1]) : 0.f;
                float e10 = (r0 + 8 >= c0    ) ? __expf(acc[mt][nt][2]) : 0.f;
                float e11 = (r0 + 8 >= c0 + 1) ? __expf(acc[mt][nt][3]) : 0.f;
                *(__nv_bfloat162*)(C + (size_t)r0 * ldc + c0) =
                    __float22bfloat162_rn(make_float2(e00, e01));
                *(__nv_bfloat162*)(C + (size_t)(r0 + 8) * ldc + c0) =
                    __float22bfloat162_rn(make_float2(e10, e11));
                cs[nt][0] += e00 + e10;
                cs[nt][1] += e01 + e11;
            }
        #pragma unroll
        for (int nt = 0; nt < 8; nt++)
            #pragma unroll
            for (int h = 0; h < 2; h++) {
                float v = cs[nt][h];
                v += __shfl_xor_sync(0xffffffffu, v, 4);
                v += __shfl_xor_sync(0xffffffffu, v, 8);
                v += __shfl_xor_sync(0xffffffffu, v, 16);
                if (lane < 4)
                    atomicAdd(psum + bz * TT + tileN + wn + nt * 8 + 2 * t4 + h, v);
            }
    } else {
        float* C = (float*)Cv + (size_t)bz * sCb;
        #pragma unroll
        for (int mt = 0; mt < 4; mt++)
            #pragma unroll
            for (int nt = 0; nt < 8; nt++) {
                int r   = tileM + wm + mt * 16 + g;
                int col = tileN + wn + nt * 8 + 2 * t4;
                float2 v0 = make_float2(acc[mt][nt][0], acc[mt][nt][1]);
                float2 v1 = make_float2(acc[mt][nt][2], acc[mt][nt][3]);
                float2 r0 = *(const float2*)(Res + (size_t)r * ldc + col);
                float2 r1 = *(const float2*)(Res + (size_t)(r + 8) * ldc + col);
                v0.x += r0.x; v0.y += r0.y;
                v1.x += r1.x; v1.y += r1.y;
                *(float2*)(C + (size_t)r * ldc + col)       = v0;
                *(float2*)(C + (size_t)(r + 8) * ldc + col) = v1;
            }
    }
}

// ---------------- transpose W (3x 1024x1024 fp32) -> Wt[3072][1024] bf16 -----
__global__ void k_transposeW(const float* __restrict__ Wq,
                             const float* __restrict__ Wk,
                             const float* __restrict__ Wv,
                             __nv_bfloat16* __restrict__ Wt)
{
    __shared__ float s[32][33];
    const int nb = blockIdx.x * 32;
    const int kb = blockIdx.y * 32;
    const float* W = (nb < 1024) ? Wq : (nb < 2048 ? Wk : Wv);
    const int nl = nb & 1023;
    const int tx = threadIdx.x, ty = threadIdx.y;
    #pragma unroll
    for (int r = 0; r < 4; r++) {
        int k = kb + ty + r * 8;
        s[ty + r * 8][tx] = W[k * 1024 + nl + tx];
    }
    __syncthreads();
    #pragma unroll
    for (int r = 0; r < 4; r++) {
        int n = nb + ty + r * 8;
        Wt[(size_t)n * 1024 + kb + tx] = __float2bfloat16(s[tx][ty + r * 8]);
    }
}

// ---------------- bias concat + psum zero --------------------------------------
__global__ void k_prep(const float* __restrict__ bq, const float* __restrict__ bk,
                       const float* __restrict__ bv, float* __restrict__ biasc,
                       float* __restrict__ psum)
{
    int i = blockIdx.x * 256 + threadIdx.x;   // 16384
    psum[i] = 0.f;
    if (i < 3072)
        biasc[i] = (i < 1024) ? bq[i] : (i < 2048 ? bk[i - 1024] : bv[i - 2048]);
}

// ---------------- X fp32 -> bf16 ------------------------------------------------
__global__ void k_cvtX(const float4* __restrict__ in, __nv_bfloat162* __restrict__ o)
{
    int i = blockIdx.x * 256 + threadIdx.x;
    float4 v = in[i];
    o[2 * i]     = __float22bfloat162_rn(make_float2(v.x, v.y));
    o[2 * i + 1] = __float22bfloat162_rn(make_float2(v.z, v.w));
}

// ------ transpose V slice of QKV -> Vt[b][v][t], scaled by 1/(32*psum[t]) ------
__global__ void k_transposeVS(const __nv_bfloat16* __restrict__ QKV,
                              const float* __restrict__ psum,
                              __nv_bfloat16* __restrict__ Vt)
{
    __shared__ __nv_bfloat16 s[32][34];
    const int tb = blockIdx.x * 32;
    const int vb = blockIdx.y * 32;
    const int b  = blockIdx.z;
    const int tx = threadIdx.x, ty = threadIdx.y;
    #pragma unroll
    for (int r = 0; r < 4; r++) {
        int t = tb + ty + r * 8;
        s[ty + r * 8][tx] = QKV[((size_t)(b * TT + t)) * 3072 + 2048 + vb + tx];
    }
    __syncthreads();
    float iv = 1.0f / (psum[b * TT + tb + tx] * 32.0f);
    #pragma unroll
    for (int r = 0; r < 4; r++) {
        int v = vb + ty + r * 8;
        Vt[(size_t)b * DD * TT + (size_t)v * TT + tb + tx] =
            __float2bfloat16(__bfloat162float(s[tx][ty + r * 8]) * iv);
    }
}

// ---------------- launch --------------------------------------------------------
extern "C" void kernel_launch(void* const* d_in, const int* in_sizes, int n_in,
                              void* d_out, int out_size)
{
    (void)in_sizes; (void)n_in; (void)out_size;
    const float* X  = (const float*)d_in[0];
    const float* Wq = (const float*)d_in[1];
    const float* bq = (const float*)d_in[2];
    const float* Wk = (const float*)d_in[3];
    const float* bk = (const float*)d_in[4];
    const float* Wv = (const float*)d_in[5];
    const float* bv = (const float*)d_in[6];
    float* out = (float*)d_out;

    __nv_bfloat16 *Xb, *Wt, *QKV, *probs, *Vt;
    float *biasc, *psum;
    cudaGetSymbolAddress((void**)&Xb,    g_Xb);
    cudaGetSymbolAddress((void**)&Wt,    g_Wt);
    cudaGetSymbolAddress((void**)&biasc, g_biasc);
    cudaGetSymbolAddress((void**)&QKV,   g_QKV);
    cudaGetSymbolAddress((void**)&probs, g_probs);
    cudaGetSymbolAddress((void**)&Vt,    g_Vt);
    cudaGetSymbolAddress((void**)&psum,  g_psum);

    cudaFuncSetAttribute(gemm_bf16<0>, cudaFuncAttributeMaxDynamicSharedMemorySize,
                         SMEM_BYTES);
    cudaFuncSetAttribute(gemm_bf16<1>, cudaFuncAttributeMaxDynamicSharedMemorySize,
                         SMEM_BYTES);
    cudaFuncSetAttribute(gemm_bf16<2>, cudaFuncAttributeMaxDynamicSharedMemorySize,
                         SMEM_BYTES);

    // 1) preprocessing
    k_transposeW<<<dim3(96, 32), dim3(32, 8)>>>(Wq, Wk, Wv, Wt);
    k_prep<<<64, 256>>>(bq, bk, bv, biasc, psum);
    k_cvtX<<<16384, 256>>>((const float4*)X, (__nv_bfloat162*)Xb);

    // 2) QKV[16384,3072] = Xb @ Wt^T + biasc  (bf16 out)
    gemm_bf16<0><<<dim3(24, 128, 1), 128, SMEM_BYTES>>>(
        Xb, Wt, QKV, biasc, nullptr, nullptr,
        1024, 1024, 3072, 1024,
        0LL, 0LL, 0LL, 0LL);

    // 3) p~[b] = causal(exp(Q[b] @ K[b]^T)) bf16; column sums -> psum
    gemm_bf16<1><<<dim3(16, 16, 8), 128, SMEM_BYTES>>>(
        QKV, QKV + 1024, probs, nullptr, nullptr, psum,
        3072, 3072, 2048, 1024,
        (long long)TT * 3072, (long long)TT * 3072, (long long)TT * TT, 0LL);

    // 4) V transpose + scale by 1/(32*psum) -> Vt[b][v][t]
    k_transposeVS<<<dim3(64, 32, 8), dim3(32, 8)>>>(QKV, psum, Vt);

    // 5) out[b] = X[b] + p~[b] @ Vt'[b]^T  (causal-truncated K, longest-first)
    gemm_bf16<2><<<dim3(8, 16, 8), 128, SMEM_BYTES>>>(
        probs, Vt, out, nullptr, X, nullptr,
        2048, 2048, 1024, 2048,
        (long long)TT * TT, (long long)DD * TT, (long long)TT * DD,
        (long long)TT * DD);
}

// round 13
// speedup vs baseline: 1.4052x; 1.1139x over previous
#include <cuda_runtime.h>
#include <cuda_bf16.h>
#include <cstdint>

// ---------------------------------------------------------------------------
// AttentionBlock: out = X + softmax_axis1(causal(Q K^T))/sqrt(k) @ V
// B=8, T=2048, D=1024. bf16 mma.sync GEMMs. 3 CTAs/SM, BKH=64 (128B rows,
// XOR-swizzled, conflict-free), 2-stage pipeline with one sync per stage.
// Softmax fused into GEMM2 epilogue, normalization folded into V.
// ---------------------------------------------------------------------------

#define BATCH 8
#define TT    2048
#define DD    1024

#define BM 128
#define BN 128
#define BKH 64                          // bf16 k-elems per stage (128 B rows)
#define NST 2
#define TILE_B  16384                   // 128 rows x 128 bytes
#define STAGE_B (2 * TILE_B)            // 32768
#define SMEM_BYTES (NST * STAGE_B)      // 65536 -> 3 CTAs/SM = 192 KB

// ---------------- scratch (device globals; no allocation allowed) ----------
__device__ __nv_bfloat16 g_Xb[(size_t)16384 * 1024];
__device__ __nv_bfloat16 g_Wt[(size_t)3072 * 1024];        // [n][k] = W[k][n]
__device__ float         g_biasc[3072];
__device__ __nv_bfloat16 g_QKV[(size_t)16384 * 3072];      // [b*T + t][3072]
__device__ __nv_bfloat16 g_probs[(size_t)BATCH * TT * TT]; // p~ = exp(logit)
__device__ __nv_bfloat16 g_Vt[(size_t)BATCH * DD * TT];    // [b][v][t] * inv[t]
__device__ float         g_psum[BATCH * TT];

// ---------------- helpers ----------------------------------------------------
__device__ __forceinline__ void cp16(uint32_t s, const void* g) {
    asm volatile("cp.async.cg.shared.global [%0], [%1], 16;" :: "r"(s), "l"(g));
}
__device__ __forceinline__ void ldsm_x4(uint32_t* r, uint32_t saddr) {
    asm volatile("ldmatrix.sync.aligned.m8n8.x4.shared.b16 {%0,%1,%2,%3}, [%4];"
        : "=r"(r[0]), "=r"(r[1]), "=r"(r[2]), "=r"(r[3]) : "r"(saddr));
}
__device__ __forceinline__ void mma16816(float* d, const uint32_t* a,
                                         uint32_t b0, uint32_t b1) {
    asm volatile(
        "mma.sync.aligned.m16n8k16.row.col.f32.bf16.bf16.f32 "
        "{%0,%1,%2,%3},{%4,%5,%6,%7},{%8,%9},{%0,%1,%2,%3};\n"
        : "+f"(d[0]), "+f"(d[1]), "+f"(d[2]), "+f"(d[3])
        : "r"(a[0]), "r"(a[1]), "r"(a[2]), "r"(a[3]), "r"(b0), "r"(b1));
}

// ---------------- bf16 GEMM: C[m][n] = sum_k A[m][k]*B[n][k] ------------------
// CTA 128x128, 128 threads, 4 warps (2x2), warp tile 64x64, 3 CTAs/SM.
// smem row = 128 B; store off = row*128 + ((k16*16) ^ ((row&7)*16)).
// MODE 0: out bf16 += bias[n]                              (QKV projection)
// MODE 1: out bf16 = causal(exp(acc)); column sums -> psum (logits/probs);
//         tiles strictly above diagonal return (never read downstream).
// MODE 2: out fp32 += Res; k-loop truncated at tileM+BM; y reversed so the
//         longest tiles launch first (wave packing).                   (AV)
template<int MODE>
__global__ void __launch_bounds__(128, 3)
gemm_bf16(const __nv_bfloat16* __restrict__ A, const __nv_bfloat16* __restrict__ B,
          void* __restrict__ Cv,
          const float* __restrict__ bias, const float* __restrict__ Res,
          float* __restrict__ psum,
          int lda, int ldb, int ldc, int K,
          long long sAb, long long sBb, long long sCb, long long sRb)
{
    extern __shared__ __align__(1024) char smem[];
    const int tid = threadIdx.x;
    const int bz  = blockIdx.z;
    const int by  = (MODE == 2) ? (gridDim.y - 1 - blockIdx.y) : blockIdx.y;
    const int tileM = by * BM;
    const int tileN = blockIdx.x * BN;

    if (MODE == 1 && tileN >= tileM + BM) return;   // never read by GEMM3

    A += (size_t)bz * sAb;
    B += (size_t)bz * sBb;
    if (MODE == 2) Res += (size_t)bz * sRb;

    const int wid = tid >> 5, lane = tid & 31;
    const int g = lane >> 2, t4 = lane & 3;
    const int wm = (wid >> 1) * 64;
    const int wn = (wid & 1) * 64;

    const int lj = lane >> 3, lr = lane & 7;
    const int mrow = (lj & 1) * 8 + lr;     // row within 16-row tile (&7 == lr)
    const int klo  = (lj >> 1) * 16;        // byte offset within k16 step
    const int swz  = lr * 16;               // XOR key (row&7)*16

    float acc[4][8][4];
    #pragma unroll
    for (int i = 0; i < 4; i++)
        #pragma unroll
        for (int j = 0; j < 8; j++)
            #pragma unroll
            for (int k = 0; k < 4; k++) acc[i][j][k] = 0.f;

    const uint32_t smem_u = (uint32_t)__cvta_generic_to_shared(smem);

    // fill: thread owns rows (tid>>3)+{0,16,...,112}, 16B chunk (tid&7).
    // XOR key depends only on row&7 (stable under +16 row steps).
    const int frow = tid >> 3, fc = tid & 7;
    const __nv_bfloat16* gA = A + (size_t)(tileM + frow) * lda + fc * 8;
    const __nv_bfloat16* gB = B + (size_t)(tileN + frow) * ldb + fc * 8;
    const uint32_t sOff = (uint32_t)(frow * 128 + ((fc * 16) ^ ((frow & 7) * 16)));

    auto fill = [&](int s) {
        const uint32_t base = smem_u + (s & 1) * STAGE_B + sOff;
        const int kk = s * BKH;
        #pragma unroll
        for (int i = 0; i < 8; i++)
            cp16(base + i * 16 * 128, gA + (size_t)i * 16 * lda + kk);
        #pragma unroll
        for (int i = 0; i < 8; i++)
            cp16(base + TILE_B + i * 16 * 128, gB + (size_t)i * 16 * ldb + kk);
    };

    const int Keff = (MODE == 2) ? (tileM + BM) : K;
    const int KT = Keff / BKH;                       // >= 2

    fill(0);
    asm volatile("cp.async.commit_group;");

    for (int s = 0; s < KT; s++) {
        asm volatile("cp.async.wait_group 0;");
        __syncthreads();                 // stage s ready; prev compute done

        if (s + 1 < KT) {
            fill(s + 1);                 // other buffer; overlaps compute(s)
            asm volatile("cp.async.commit_group;");
        }

        const uint32_t stg = smem_u + (uint32_t)((s & 1) * STAGE_B);
        const uint32_t aBase = stg + (uint32_t)((wm + mrow) * 128);
        const uint32_t bBase = stg + TILE_B + (uint32_t)((wn + mrow) * 128);

        #pragma unroll
        for (int ks = 0; ks < 4; ks++) {            // 4 k16-steps per stage
            const uint32_t kb = (uint32_t)((ks * 32 + klo) ^ swz);
            uint32_t qf[4][4];
            ldsm_x4(qf[0], bBase + 0 * 16 * 128 + kb);
            ldsm_x4(qf[1], bBase + 1 * 16 * 128 + kb);
            ldsm_x4(qf[2], bBase + 2 * 16 * 128 + kb);
            ldsm_x4(qf[3], bBase + 3 * 16 * 128 + kb);
            uint32_t af[2][4];
            ldsm_x4(af[0], aBase + kb);
            #pragma unroll
            for (int mt = 0; mt < 4; mt++) {
                const int cur = mt & 1;
                if (mt < 3)
                    ldsm_x4(af[cur ^ 1], aBase + (mt + 1) * 16 * 128 + kb);
                #pragma unroll
                for (int np = 0; np < 4; np++)
                    #pragma unroll
                    for (int h = 0; h < 2; h++)
                        mma16816(acc[mt][np * 2 + h], af[cur],
                                 qf[np][h], qf[np][h + 2]);
            }
        }
    }

    // ---------------- epilogues ----------------
    if (MODE == 0) {
        __nv_bfloat16* C = (__nv_bfloat16*)Cv + (size_t)bz * sCb;
        #pragma unroll
        for (int mt = 0; mt < 4; mt++)
            #pragma unroll
            for (int nt = 0; nt < 8; nt++) {
                int r   = tileM + wm + mt * 16 + g;
                int col = tileN + wn + nt * 8 + 2 * t4;
                float2 bb = *(const float2*)(bias + col);
                float2 v0 = make_float2(acc[mt][nt][0] + bb.x, acc[mt][nt][1] + bb.y);
                float2 v1 = make_float2(acc[mt][nt][2] + bb.x, acc[mt][nt][3] + bb.y);
                *(__nv_bfloat162*)(C + (size_t)r * ldc + col) =
                    __float22bfloat162_rn(v0);
                *(__nv_bfloat162*)(C + (size_t)(r + 8) * ldc + col) =
                    __float22bfloat162_rn(v1);
            }
    } else if (MODE == 1) {
        __nv_bfloat16* C = (__nv_bfloat16*)Cv + (size_t)bz * sCb;
        float cs[8][2];
        #pragma unroll
        for (int nt = 0; nt < 8; nt++) { cs[nt][0] = 0.f; cs[nt][1] = 0.f; }
        #pragma unroll
        for (int mt = 0; mt < 4; mt++)
            #pragma unroll
            for (int nt = 0; nt < 8; nt++) {
                int r0 = tileM + wm + mt * 16 + g;
                int c0 = tileN + wn + nt * 8 + 2 * t4;
                float e00 = (r0     >= c0    ) ? __expf(acc[mt][nt][0]) : 0.f;
                float e01 = (r0     >= c0 + 1) ? __expf(acc[mt][nt][1]) : 0.f;
                float e10 = (r0 + 8 >= c0    ) ? __expf(acc[mt][nt][2]) : 0.f;
                float e11 = (r0 + 8 >= c0 + 1) ? __expf(acc[mt][nt][3]) : 0.f;
                *(__nv_bfloat162*)(C + (size_t)r0 * ldc + c0) =
                    __float22bfloat162_rn(make_float2(e00, e01));
                *(__nv_bfloat162*)(C + (size_t)(r0 + 8) * ldc + c0) =
                    __float22bfloat162_rn(make_float2(e10, e11));
                cs[nt][0] += e00 + e10;
                cs[nt][1] += e01 + e11;
            }
        #pragma unroll
        for (int nt = 0; nt < 8; nt++)
            #pragma unroll
            for (int h = 0; h < 2; h++) {
                float v = cs[nt][h];
                v += __shfl_xor_sync(0xffffffffu, v, 4);
                v += __shfl_xor_sync(0xffffffffu, v, 8);
                v += __shfl_xor_sync(0xffffffffu, v, 16);
                if (lane < 4)
                    atomicAdd(psum + bz * TT + tileN + wn + nt * 8 + 2 * t4 + h, v);
            }
    } else {
        float* C = (float*)Cv + (size_t)bz * sCb;
        #pragma unroll
        for (int mt = 0; mt < 4; mt++)
            #pragma unroll
            for (int nt = 0; nt < 8; nt++) {
                int r   = tileM + wm + mt * 16 + g;
                int col = tileN + wn + nt * 8 + 2 * t4;
                float2 v0 = make_float2(acc[mt][nt][0], acc[mt][nt][1]);
                float2 v1 = make_float2(acc[mt][nt][2], acc[mt][nt][3]);
                float2 r0 = *(const float2*)(Res + (size_t)r * ldc + col);
                float2 r1 = *(const float2*)(Res + (size_t)(r + 8) * ldc + col);
                v0.x += r0.x; v0.y += r0.y;
                v1.x += r1.x; v1.y += r1.y;
                *(float2*)(C + (size_t)r * ldc + col)       = v0;
                *(float2*)(C + (size_t)(r + 8) * ldc + col) = v1;
            }
    }
}

// ---------------- transpose W (3x 1024x1024 fp32) -> Wt[3072][1024] bf16 -----
__global__ void k_transposeW(const float* __restrict__ Wq,
                             const float* __restrict__ Wk,
                             const float* __restrict__ Wv,
                             __nv_bfloat16* __restrict__ Wt)
{
    __shared__ float s[32][33];
    const int nb = blockIdx.x * 32;
    const int kb = blockIdx.y * 32;
    const float* W = (nb < 1024) ? Wq : (nb < 2048 ? Wk : Wv);
    const int nl = nb & 1023;
    const int tx = threadIdx.x, ty = threadIdx.y;
    #pragma unroll
    for (int r = 0; r < 4; r++) {
        int k = kb + ty + r * 8;
        s[ty + r * 8][tx] = W[k * 1024 + nl + tx];
    }
    __syncthreads();
    #pragma unroll
    for (int r = 0; r < 4; r++) {
        int n = nb + ty + r * 8;
        Wt[(size_t)n * 1024 + kb + tx] = __float2bfloat16(s[tx][ty + r * 8]);
    }
}

// ---------------- bias concat + psum zero --------------------------------------
__global__ void k_prep(const float* __restrict__ bq, const float* __restrict__ bk,
                       const float* __restrict__ bv, float* __restrict__ biasc,
                       float* __restrict__ psum)
{
    int i = blockIdx.x * 256 + threadIdx.x;   // 16384
    psum[i] = 0.f;
    if (i < 3072)
        biasc[i] = (i < 1024) ? bq[i] : (i < 2048 ? bk[i - 1024] : bv[i - 2048]);
}

// ---------------- X fp32 -> bf16 ------------------------------------------------
__global__ void k_cvtX(const float4* __restrict__ in, __nv_bfloat162* __restrict__ o)
{
    int i = blockIdx.x * 256 + threadIdx.x;
    float4 v = in[i];
    o[2 * i]     = __float22bfloat162_rn(make_float2(v.x, v.y));
    o[2 * i + 1] = __float22bfloat162_rn(make_float2(v.z, v.w));
}

// ------ transpose V slice of QKV -> Vt[b][v][t], scaled by 1/(32*psum[t]) ------
__global__ void k_transposeVS(const __nv_bfloat16* __restrict__ QKV,
                              const float* __restrict__ psum,
                              __nv_bfloat16* __restrict__ Vt)
{
    __shared__ __nv_bfloat16 s[32][34];
    const int tb = blockIdx.x * 32;
    const int vb = blockIdx.y * 32;
    const int b  = blockIdx.z;
    const int tx = threadIdx.x, ty = threadIdx.y;
    #pragma unroll
    for (int r = 0; r < 4; r++) {
        int t = tb + ty + r * 8;
        s[ty + r * 8][tx] = QKV[((size_t)(b * TT + t)) * 3072 + 2048 + vb + tx];
    }
    __syncthreads();
    float iv = 1.0f / (psum[b * TT + tb + tx] * 32.0f);
    #pragma unroll
    for (int r = 0; r < 4; r++) {
        int v = vb + ty + r * 8;
        Vt[(size_t)b * DD * TT + (size_t)v * TT + tb + tx] =
            __float2bfloat16(__bfloat162float(s[tx][ty + r * 8]) * iv);
    }
}

// ---------------- launch --------------------------------------------------------
extern "C" void kernel_launch(void* const* d_in, const int* in_sizes, int n_in,
                              void* d_out, int out_size)
{
    (void)in_sizes; (void)n_in; (void)out_size;
    const float* X  = (const float*)d_in[0];
    const float* Wq = (const float*)d_in[1];
    const float* bq = (const float*)d_in[2];
    const float* Wk = (const float*)d_in[3];
    const float* bk = (const float*)d_in[4];
    const float* Wv = (const float*)d_in[5];
    const float* bv = (const float*)d_in[6];
    float* out = (float*)d_out;

    __nv_bfloat16 *Xb, *Wt, *QKV, *probs, *Vt;
    float *biasc, *psum;
    cudaGetSymbolAddress((void**)&Xb,    g_Xb);
    cudaGetSymbolAddress((void**)&Wt,    g_Wt);
    cudaGetSymbolAddress((void**)&biasc, g_biasc);
    cudaGetSymbolAddress((void**)&QKV,   g_QKV);
    cudaGetSymbolAddress((void**)&probs, g_probs);
    cudaGetSymbolAddress((void**)&Vt,    g_Vt);
    cudaGetSymbolAddress((void**)&psum,  g_psum);

    cudaFuncSetAttribute(gemm_bf16<0>, cudaFuncAttributeMaxDynamicSharedMemorySize,
                         SMEM_BYTES);
    cudaFuncSetAttribute(gemm_bf16<1>, cudaFuncAttributeMaxDynamicSharedMemorySize,
                         SMEM_BYTES);
    cudaFuncSetAttribute(gemm_bf16<2>, cudaFuncAttributeMaxDynamicSharedMemorySize,
                         SMEM_BYTES);

    // 1) preprocessing
    k_transposeW<<<dim3(96, 32), dim3(32, 8)>>>(Wq, Wk, Wv, Wt);
    k_prep<<<64, 256>>>(bq, bk, bv, biasc, psum);
    k_cvtX<<<16384, 256>>>((const float4*)X, (__nv_bfloat162*)Xb);

    // 2) QKV[16384,3072] = Xb @ Wt^T + biasc  (bf16 out)
    gemm_bf16<0><<<dim3(24, 128, 1), 128, SMEM_BYTES>>>(
        Xb, Wt, QKV, biasc, nullptr, nullptr,
        1024, 1024, 3072, 1024,
        0LL, 0LL, 0LL, 0LL);

    // 3) p~[b] = causal(exp(Q[b] @ K[b]^T)) bf16; column sums -> psum
    gemm_bf16<1><<<dim3(16, 16, 8), 128, SMEM_BYTES>>>(
        QKV, QKV + 1024, probs, nullptr, nullptr, psum,
        3072, 3072, 2048, 1024,
        (long long)TT * 3072, (long long)TT * 3072, (long long)TT * TT, 0LL);

    // 4) V transpose + scale by 1/(32*psum) -> Vt[b][v][t]
    k_transposeVS<<<dim3(64, 32, 8), dim3(32, 8)>>>(QKV, psum, Vt);

    // 5) out[b] = X[b] + p~[b] @ Vt'[b]^T  (causal-truncated K, longest-first)
    gemm_bf16<2><<<dim3(8, 16, 8), 128, SMEM_BYTES>>>(
        probs, Vt, out, nullptr, X, nullptr,
        2048, 2048, 1024, 2048,
        (long long)TT * TT, (long long)DD * TT, (long long)TT * DD,
        (long long)TT * DD);
}

// round 14
// speedup vs baseline: 1.4666x; 1.0437x over previous
#include <cuda_runtime.h>
#include <cuda_bf16.h>
#include <cstdint>

// ---------------------------------------------------------------------------
// AttentionBlock: out = X + softmax_axis1(causal(Q K^T))/sqrt(k) @ V
// B=8, T=2048, D=1024. bf16 mma.sync GEMMs — R9 core (2 CTA/SM, NST=3,
// BKH=64, XOR-swizzled 128B rows) + GEMM3 longest-first + LDSM order tweak.
// Softmax fused into GEMM2 epilogue, normalization folded into V.
// ---------------------------------------------------------------------------

#define BATCH 8
#define TT    2048
#define DD    1024

#define BM 128
#define BN 128
#define BKH 64                          // bf16 k-elems per stage (128 B rows)
#define NST 3
#define TILE_B  16384                   // 128 rows x 128 bytes
#define STAGE_B (2 * TILE_B)            // 32768
#define SMEM_BYTES (NST * STAGE_B)      // 98304 -> 2 CTAs/SM = 192 KB

// ---------------- scratch (device globals; no allocation allowed) ----------
__device__ __nv_bfloat16 g_Xb[(size_t)16384 * 1024];
__device__ __nv_bfloat16 g_Wt[(size_t)3072 * 1024];        // [n][k] = W[k][n]
__device__ float         g_biasc[3072];
__device__ __nv_bfloat16 g_QKV[(size_t)16384 * 3072];      // [b*T + t][3072]
__device__ __nv_bfloat16 g_probs[(size_t)BATCH * TT * TT]; // p~ = exp(logit)
__device__ __nv_bfloat16 g_Vt[(size_t)BATCH * DD * TT];    // [b][v][t] * inv[t]
__device__ float         g_psum[BATCH * TT];

// ---------------- helpers ----------------------------------------------------
__device__ __forceinline__ void cp16(uint32_t s, const void* g) {
    asm volatile("cp.async.cg.shared.global [%0], [%1], 16;" :: "r"(s), "l"(g));
}
__device__ __forceinline__ void ldsm_x4(uint32_t* r, uint32_t saddr) {
    asm volatile("ldmatrix.sync.aligned.m8n8.x4.shared.b16 {%0,%1,%2,%3}, [%4];"
        : "=r"(r[0]), "=r"(r[1]), "=r"(r[2]), "=r"(r[3]) : "r"(saddr));
}
__device__ __forceinline__ void mma16816(float* d, const uint32_t* a,
                                         uint32_t b0, uint32_t b1) {
    asm volatile(
        "mma.sync.aligned.m16n8k16.row.col.f32.bf16.bf16.f32 "
        "{%0,%1,%2,%3},{%4,%5,%6,%7},{%8,%9},{%0,%1,%2,%3};\n"
        : "+f"(d[0]), "+f"(d[1]), "+f"(d[2]), "+f"(d[3])
        : "r"(a[0]), "r"(a[1]), "r"(a[2]), "r"(a[3]), "r"(b0), "r"(b1));
}

// ---------------- bf16 GEMM: C[m][n] = sum_k A[m][k]*B[n][k] ------------------
// CTA 128x128, 128 threads, 4 warps (2x2), warp tile 64x64, 2 CTAs/SM.
// smem row = 128 B; off = row*128 + ((k16*16) ^ ((row&7)*16)) — conflict-free
// for both cp.async stores and ldmatrix reads (verified R9).
// MODE 0: out bf16 += bias[n]                              (QKV projection)
// MODE 1: out bf16 = causal(exp(acc)); column sums -> psum (logits/probs);
//         tiles strictly above diagonal return (never read downstream).
// MODE 2: out fp32 += Res; k-loop truncated at tileM+BM; y reversed so the
//         longest tiles launch first (wave packing).                   (AV)
template<int MODE>
__global__ void __launch_bounds__(128, 2)
gemm_bf16(const __nv_bfloat16* __restrict__ A, const __nv_bfloat16* __restrict__ B,
          void* __restrict__ Cv,
          const float* __restrict__ bias, const float* __restrict__ Res,
          float* __restrict__ psum,
          int lda, int ldb, int ldc, int K,
          long long sAb, long long sBb, long long sCb, long long sRb)
{
    extern __shared__ __align__(1024) char smem[];
    const int tid = threadIdx.x;
    const int bz  = blockIdx.z;
    const int by  = (MODE == 2) ? (gridDim.y - 1 - blockIdx.y) : blockIdx.y;
    const int tileM = by * BM;
    const int tileN = blockIdx.x * BN;

    if (MODE == 1 && tileN >= tileM + BM) return;   // never read by GEMM3

    A += (size_t)bz * sAb;
    B += (size_t)bz * sBb;
    if (MODE == 2) Res += (size_t)bz * sRb;

    const int wid = tid >> 5, lane = tid & 31;
    const int g = lane >> 2, t4 = lane & 3;
    const int wm = (wid >> 1) * 64;
    const int wn = (wid & 1) * 64;

    const int lj = lane >> 3, lr = lane & 7;
    const int mrow = (lj & 1) * 8 + lr;     // row within 16-row tile (&7 == lr)
    const int klo  = (lj >> 1) * 16;        // byte offset within k16 step
    const int swz  = lr * 16;               // XOR key (row&7)*16

    float acc[4][8][4];
    #pragma unroll
    for (int i = 0; i < 4; i++)
        #pragma unroll
        for (int j = 0; j < 8; j++)
            #pragma unroll
            for (int k = 0; k < 4; k++) acc[i][j][k] = 0.f;

    const uint32_t smem_u = (uint32_t)__cvta_generic_to_shared(smem);

    // fill: thread owns rows (tid>>3)+{0,16,...,112}, 16B chunk (tid&7).
    // XOR key depends only on row&7 (stable under +16 row steps).
    const int frow = tid >> 3, fc = tid & 7;
    const __nv_bfloat16* gA = A + (size_t)(tileM + frow) * lda + fc * 8;
    const __nv_bfloat16* gB = B + (size_t)(tileN + frow) * ldb + fc * 8;
    const uint32_t sOff = (uint32_t)(frow * 128 + ((fc * 16) ^ ((frow & 7) * 16)));

    auto fill = [&](int s) {
        const uint32_t base = smem_u + (s % NST) * STAGE_B + sOff;
        const int kk = s * BKH;
        #pragma unroll
        for (int i = 0; i < 8; i++)
            cp16(base + i * 16 * 128, gA + (size_t)i * 16 * lda + kk);
        #pragma unroll
        for (int i = 0; i < 8; i++)
            cp16(base + TILE_B + i * 16 * 128, gB + (size_t)i * 16 * ldb + kk);
    };

    const int Keff = (MODE == 2) ? (tileM + BM) : K;
    const int KT = Keff / BKH;                       // >= 2

    fill(0);
    asm volatile("cp.async.commit_group;");
    fill(1);
    asm volatile("cp.async.commit_group;");

    for (int s = 0; s < KT; s++) {
        if (s < KT - 1) asm volatile("cp.async.wait_group 1;");
        else            asm volatile("cp.async.wait_group 0;");
        __syncthreads();

        if (s + 2 < KT) {
            fill(s + 2);
            asm volatile("cp.async.commit_group;");
        }

        const uint32_t stg = smem_u + (uint32_t)((s % NST) * STAGE_B);
        const uint32_t aBase = stg + (uint32_t)((wm + mrow) * 128);
        const uint32_t bBase = stg + TILE_B + (uint32_t)((wn + mrow) * 128);

        #pragma unroll
        for (int ks = 0; ks < 4; ks++) {            // 4 k16-steps per stage
            const uint32_t kb = (uint32_t)((ks * 32 + klo) ^ swz);
            // issue af[0] FIRST so the first dependent HMMA waits on the
            // oldest LDSM (shrinks head-of-kstep bubble)
            uint32_t af[2][4];
            ldsm_x4(af[0], aBase + kb);
            uint32_t qf[4][4];
            ldsm_x4(qf[0], bBase + 0 * 16 * 128 + kb);
            ldsm_x4(qf[1], bBase + 1 * 16 * 128 + kb);
            ldsm_x4(qf[2], bBase + 2 * 16 * 128 + kb);
            ldsm_x4(qf[3], bBase + 3 * 16 * 128 + kb);
            #pragma unroll
            for (int mt = 0; mt < 4; mt++) {
                const int cur = mt & 1;
                if (mt < 3)
                    ldsm_x4(af[cur ^ 1], aBase + (mt + 1) * 16 * 128 + kb);
                #pragma unroll
                for (int np = 0; np < 4; np++)
                    #pragma unroll
                    for (int h = 0; h < 2; h++)
                        mma16816(acc[mt][np * 2 + h], af[cur],
                                 qf[np][h], qf[np][h + 2]);
            }
        }
    }

    // ---------------- epilogues ----------------
    if (MODE == 0) {
        __nv_bfloat16* C = (__nv_bfloat16*)Cv + (size_t)bz * sCb;
        #pragma unroll
        for (int mt = 0; mt < 4; mt++)
            #pragma unroll
            for (int nt = 0; nt < 8; nt++) {
                int r   = tileM + wm + mt * 16 + g;
                int col = tileN + wn + nt * 8 + 2 * t4;
                float2 bb = *(const float2*)(bias + col);
                float2 v0 = make_float2(acc[mt][nt][0] + bb.x, acc[mt][nt][1] + bb.y);
                float2 v1 = make_float2(acc[mt][nt][2] + bb.x, acc[mt][nt][3] + bb.y);
                *(__nv_bfloat162*)(C + (size_t)r * ldc + col) =
                    __float22bfloat162_rn(v0);
                *(__nv_bfloat162*)(C + (size_t)(r + 8) * ldc + col) =
                    __float22bfloat162_rn(v1);
            }
    } else if (MODE == 1) {
        __nv_bfloat16* C = (__nv_bfloat16*)Cv + (size_t)bz * sCb;
        float cs[8][2];
        #pragma unroll
        for (int nt = 0; nt < 8; nt++) { cs[nt][0] = 0.f; cs[nt][1] = 0.f; }
        #pragma unroll
        for (int mt = 0; mt < 4; mt++)
            #pragma unroll
            for (int nt = 0; nt < 8; nt++) {
                int r0 = tileM + wm + mt * 16 + g;
                int c0 = tileN + wn + nt * 8 + 2 * t4;
                float e00 = (r0     >= c0    ) ? __expf(acc[mt][nt][0]) : 0.f;
                float e01 = (r0     >= c0 + 1) ? __expf(acc[mt][nt][1]) : 0.f;
                float e10 = (r0 + 8 >= c0    ) ? __expf(acc[mt][nt][2]) : 0.f;
                float e11 = (r0 + 8 >= c0 + 1) ? __expf(acc[mt][nt][3]) : 0.f;
                *(__nv_bfloat162*)(C + (size_t)r0 * ldc + c0) =
                    __float22bfloat162_rn(make_float2(e00, e01));
                *(__nv_bfloat162*)(C + (size_t)(r0 + 8) * ldc + c0) =
                    __float22bfloat162_rn(make_float2(e10, e11));
                cs[nt][0] += e00 + e10;
                cs[nt][1] += e01 + e11;
            }
        #pragma unroll
        for (int nt = 0; nt < 8; nt++)
            #pragma unroll
            for (int h = 0; h < 2; h++) {
                float v = cs[nt][h];
                v += __shfl_xor_sync(0xffffffffu, v, 4);
                v += __shfl_xor_sync(0xffffffffu, v, 8);
                v += __shfl_xor_sync(0xffffffffu, v, 16);
                if (lane < 4)
                    atomicAdd(psum + bz * TT + tileN + wn + nt * 8 + 2 * t4 + h, v);
            }
    } else {
        float* C = (float*)Cv + (size_t)bz * sCb;
        #pragma unroll
        for (int mt = 0; mt < 4; mt++)
            #pragma unroll
            for (int nt = 0; nt < 8; nt++) {
                int r   = tileM + wm + mt * 16 + g;
                int col = tileN + wn + nt * 8 + 2 * t4;
                float2 v0 = make_float2(acc[mt][nt][0], acc[mt][nt][1]);
                float2 v1 = make_float2(acc[mt][nt][2], acc[mt][nt][3]);
                float2 r0 = *(const float2*)(Res + (size_t)r * ldc + col);
                float2 r1 = *(const float2*)(Res + (size_t)(r + 8) * ldc + col);
                v0.x += r0.x; v0.y += r0.y;
                v1.x += r1.x; v1.y += r1.y;
                *(float2*)(C + (size_t)r * ldc + col)       = v0;
                *(float2*)(C + (size_t)(r + 8) * ldc + col) = v1;
            }
    }
}

// ---------------- transpose W (3x 1024x1024 fp32) -> Wt[3072][1024] bf16 -----
__global__ void k_transposeW(const float* __restrict__ Wq,
                             const float* __restrict__ Wk,
                             const float* __restrict__ Wv,
                             __nv_bfloat16* __restrict__ Wt)
{
    __shared__ float s[32][33];
    const int nb = blockIdx.x * 32;
    const int kb = blockIdx.y * 32;
    const float* W = (nb < 1024) ? Wq : (nb < 2048 ? Wk : Wv);
    const int nl = nb & 1023;
    const int tx = threadIdx.x, ty = threadIdx.y;
    #pragma unroll
    for (int r = 0; r < 4; r++) {
        int k = kb + ty + r * 8;
        s[ty + r * 8][tx] = W[k * 1024 + nl + tx];
    }
    __syncthreads();
    #pragma unroll
    for (int r = 0; r < 4; r++) {
        int n = nb + ty + r * 8;
        Wt[(size_t)n * 1024 + kb + tx] = __float2bfloat16(s[tx][ty + r * 8]);
    }
}

// ---------------- bias concat + psum zero --------------------------------------
__global__ void k_prep(const float* __restrict__ bq, const float* __restrict__ bk,
                       const float* __restrict__ bv, float* __restrict__ biasc,
                       float* __restrict__ psum)
{
    int i = blockIdx.x * 256 + threadIdx.x;   // 16384
    psum[i] = 0.f;
    if (i < 3072)
        biasc[i] = (i < 1024) ? bq[i] : (i < 2048 ? bk[i - 1024] : bv[i - 2048]);
}

// ---------------- X fp32 -> bf16 ------------------------------------------------
__global__ void k_cvtX(const float4* __restrict__ in, __nv_bfloat162* __restrict__ o)
{
    int i = blockIdx.x * 256 + threadIdx.x;
    float4 v = in[i];
    o[2 * i]     = __float22bfloat162_rn(make_float2(v.x, v.y));
    o[2 * i + 1] = __float22bfloat162_rn(make_float2(v.z, v.w));
}

// ------ transpose V slice of QKV -> Vt[b][v][t], scaled by 1/(32*psum[t]) ------
__global__ void k_transposeVS(const __nv_bfloat16* __restrict__ QKV,
                              const float* __restrict__ psum,
                              __nv_bfloat16* __restrict__ Vt)
{
    __shared__ __nv_bfloat16 s[32][34];
    const int tb = blockIdx.x * 32;
    const int vb = blockIdx.y * 32;
    const int b  = blockIdx.z;
    const int tx = threadIdx.x, ty = threadIdx.y;
    #pragma unroll
    for (int r = 0; r < 4; r++) {
        int t = tb + ty + r * 8;
        s[ty + r * 8][tx] = QKV[((size_t)(b * TT + t)) * 3072 + 2048 + vb + tx];
    }
    __syncthreads();
    float iv = 1.0f / (psum[b * TT + tb + tx] * 32.0f);
    #pragma unroll
    for (int r = 0; r < 4; r++) {
        int v = vb + ty + r * 8;
        Vt[(size_t)b * DD * TT + (size_t)v * TT + tb + tx] =
            __float2bfloat16(__bfloat162float(s[tx][ty + r * 8]) * iv);
    }
}

// ---------------- launch --------------------------------------------------------
extern "C" void kernel_launch(void* const* d_in, const int* in_sizes, int n_in,
                              void* d_out, int out_size)
{
    (void)in_sizes; (void)n_in; (void)out_size;
    const float* X  = (const float*)d_in[0];
    const float* Wq = (const float*)d_in[1];
    const float* bq = (const float*)d_in[2];
    const float* Wk = (const float*)d_in[3];
    const float* bk = (const float*)d_in[4];
    const float* Wv = (const float*)d_in[5];
    const float* bv = (const float*)d_in[6];
    float* out = (float*)d_out;

    __nv_bfloat16 *Xb, *Wt, *QKV, *probs, *Vt;
    float *biasc, *psum;
    cudaGetSymbolAddress((void**)&Xb,    g_Xb);
    cudaGetSymbolAddress((void**)&Wt,    g_Wt);
    cudaGetSymbolAddress((void**)&biasc, g_biasc);
    cudaGetSymbolAddress((void**)&QKV,   g_QKV);
    cudaGetSymbolAddress((void**)&probs, g_probs);
    cudaGetSymbolAddress((void**)&Vt,    g_Vt);
    cudaGetSymbolAddress((void**)&psum,  g_psum);

    cudaFuncSetAttribute(gemm_bf16<0>, cudaFuncAttributeMaxDynamicSharedMemorySize,
                         SMEM_BYTES);
    cudaFuncSetAttribute(gemm_bf16<1>, cudaFuncAttributeMaxDynamicSharedMemorySize,
                         SMEM_BYTES);
    cudaFuncSetAttribute(gemm_bf16<2>, cudaFuncAttributeMaxDynamicSharedMemorySize,
                         SMEM_BYTES);

    // 1) preprocessing
    k_transposeW<<<dim3(96, 32), dim3(32, 8)>>>(Wq, Wk, Wv, Wt);
    k_prep<<<64, 256>>>(bq, bk, bv, biasc, psum);
    k_cvtX<<<16384, 256>>>((const float4*)X, (__nv_bfloat162*)Xb);

    // 2) QKV[16384,3072] = Xb @ Wt^T + biasc  (bf16 out)
    gemm_bf16<0><<<dim3(24, 128, 1), 128, SMEM_BYTES>>>(
        Xb, Wt, QKV, biasc, nullptr, nullptr,
        1024, 1024, 3072, 1024,
        0LL, 0LL, 0LL, 0LL);

    // 3) p~[b] = causal(exp(Q[b] @ K[b]^T)) bf16; column sums -> psum
    gemm_bf16<1><<<dim3(16, 16, 8), 128, SMEM_BYTES>>>(
        QKV, QKV + 1024, probs, nullptr, nullptr, psum,
        3072, 3072, 2048, 1024,
        (long long)TT * 3072, (long long)TT * 3072, (long long)TT * TT, 0LL);

    // 4) V transpose + scale by 1/(32*psum) -> Vt[b][v][t]
    k_transposeVS<<<dim3(64, 32, 8), dim3(32, 8)>>>(QKV, psum, Vt);

    // 5) out[b] = X[b] + p~[b] @ Vt'[b]^T  (causal-truncated K, longest-first)
    gemm_bf16<2><<<dim3(8, 16, 8), 128, SMEM_BYTES>>>(
        probs, Vt, out, nullptr, X, nullptr,
        2048, 2048, 1024, 2048,
        (long long)TT * TT, (long long)DD * TT, (long long)TT * DD,
        (long long)TT * DD);
}

// round 15
// speedup vs baseline: 1.5189x; 1.0357x over previous
#include <cuda_runtime.h>
#include <cuda_bf16.h>
#include <cstdint>

// ---------------------------------------------------------------------------
// AttentionBlock: out = X + softmax_axis1(causal(Q K^T))/sqrt(k) @ V
// B=8, T=2048, D=1024. bf16 mma.sync GEMMs — R9/R14 core (2 CTA/SM, NST=3,
// BKH=64, XOR-swizzled 128B rows), compile-time leading dims, GEMM3
// longest-first. Softmax fused into GEMM2 epilogue, norm folded into V.
// Vectorized 64x64 V-transpose; merged preprocessing kernel.
// ---------------------------------------------------------------------------

#define BATCH 8
#define TT    2048
#define DD    1024

#define BM 128
#define BN 128
#define BKH 64                          // bf16 k-elems per stage (128 B rows)
#define NST 3
#define TILE_B  16384                   // 128 rows x 128 bytes
#define STAGE_B (2 * TILE_B)            // 32768
#define SMEM_BYTES (NST * STAGE_B)      // 98304 -> 2 CTAs/SM

// ---------------- scratch (device globals; no allocation allowed) ----------
__device__ __nv_bfloat16 g_Xb[(size_t)16384 * 1024];
__device__ __nv_bfloat16 g_Wt[(size_t)3072 * 1024];        // [n][k] = W[k][n]
__device__ float         g_biasc[3072];
__device__ __nv_bfloat16 g_QKV[(size_t)16384 * 3072];      // [b*T + t][3072]
__device__ __nv_bfloat16 g_probs[(size_t)BATCH * TT * TT]; // p~ = exp(logit)
__device__ __nv_bfloat16 g_Vt[(size_t)BATCH * DD * TT];    // [b][v][t] * inv[t]
__device__ float         g_psum[BATCH * TT];

// ---------------- helpers ----------------------------------------------------
__device__ __forceinline__ void cp16(uint32_t s, const void* g) {
    asm volatile("cp.async.cg.shared.global [%0], [%1], 16;" :: "r"(s), "l"(g));
}
__device__ __forceinline__ void ldsm_x4(uint32_t* r, uint32_t saddr) {
    asm volatile("ldmatrix.sync.aligned.m8n8.x4.shared.b16 {%0,%1,%2,%3}, [%4];"
        : "=r"(r[0]), "=r"(r[1]), "=r"(r[2]), "=r"(r[3]) : "r"(saddr));
}
__device__ __forceinline__ void mma16816(float* d, const uint32_t* a,
                                         uint32_t b0, uint32_t b1) {
    asm volatile(
        "mma.sync.aligned.m16n8k16.row.col.f32.bf16.bf16.f32 "
        "{%0,%1,%2,%3},{%4,%5,%6,%7},{%8,%9},{%0,%1,%2,%3};\n"
        : "+f"(d[0]), "+f"(d[1]), "+f"(d[2]), "+f"(d[3])
        : "r"(a[0]), "r"(a[1]), "r"(a[2]), "r"(a[3]), "r"(b0), "r"(b1));
}

// ---------------- bf16 GEMM: C[m][n] = sum_k A[m][k]*B[n][k] ------------------
// CTA 128x128, 128 threads, 4 warps (2x2), warp tile 64x64, 2 CTAs/SM.
// Leading dims LDA/LDB/LDC are compile-time (address math folds to imms).
// MODE 0: out bf16 += bias[n]                              (QKV projection)
// MODE 1: out bf16 = causal(exp(acc)); column sums -> psum (logits/probs);
//         tiles strictly above diagonal return (never read downstream).
// MODE 2: out fp32 += Res; k-loop truncated at tileM+BM; y reversed so the
//         longest tiles launch first (wave packing).                   (AV)
template<int MODE, int LDA, int LDB, int LDC>
__global__ void __launch_bounds__(128, 2)
gemm_bf16(const __nv_bfloat16* __restrict__ A, const __nv_bfloat16* __restrict__ B,
          void* __restrict__ Cv,
          const float* __restrict__ bias, const float* __restrict__ Res,
          float* __restrict__ psum, int K,
          long long sAb, long long sBb, long long sCb, long long sRb)
{
    extern __shared__ __align__(1024) char smem[];
    const int tid = threadIdx.x;
    const int bz  = blockIdx.z;
    const int by  = (MODE == 2) ? (gridDim.y - 1 - blockIdx.y) : blockIdx.y;
    const int tileM = by * BM;
    const int tileN = blockIdx.x * BN;

    if (MODE == 1 && tileN >= tileM + BM) return;   // never read by GEMM3

    A += (size_t)bz * sAb;
    B += (size_t)bz * sBb;
    if (MODE == 2) Res += (size_t)bz * sRb;

    const int wid = tid >> 5, lane = tid & 31;
    const int g = lane >> 2, t4 = lane & 3;
    const int wm = (wid >> 1) * 64;
    const int wn = (wid & 1) * 64;

    const int lj = lane >> 3, lr = lane & 7;
    const int mrow = (lj & 1) * 8 + lr;     // row within 16-row tile (&7 == lr)
    const int klo  = (lj >> 1) * 16;        // byte offset within k16 step
    const int swz  = lr * 16;               // XOR key (row&7)*16

    float acc[4][8][4];
    #pragma unroll
    for (int i = 0; i < 4; i++)
        #pragma unroll
        for (int j = 0; j < 8; j++)
            #pragma unroll
            for (int k = 0; k < 4; k++) acc[i][j][k] = 0.f;

    const uint32_t smem_u = (uint32_t)__cvta_generic_to_shared(smem);

    // fill: thread owns rows (tid>>3)+{0,16,...,112}, 16B chunk (tid&7).
    const int frow = tid >> 3, fc = tid & 7;
    const __nv_bfloat16* gA = A + (size_t)(tileM + frow) * LDA + fc * 8;
    const __nv_bfloat16* gB = B + (size_t)(tileN + frow) * LDB + fc * 8;
    const uint32_t sOff = (uint32_t)(frow * 128 + ((fc * 16) ^ ((frow & 7) * 16)));

    auto fill = [&](int s) {
        const uint32_t base = smem_u + (s % NST) * STAGE_B + sOff;
        const int kk = s * BKH;
        #pragma unroll
        for (int i = 0; i < 8; i++)
            cp16(base + i * 16 * 128, gA + (size_t)i * 16 * LDA + kk);
        #pragma unroll
        for (int i = 0; i < 8; i++)
            cp16(base + TILE_B + i * 16 * 128, gB + (size_t)i * 16 * LDB + kk);
    };

    const int Keff = (MODE == 2) ? (tileM + BM) : K;
    const int KT = Keff / BKH;                       // >= 2

    fill(0);
    asm volatile("cp.async.commit_group;");
    fill(1);
    asm volatile("cp.async.commit_group;");

    for (int s = 0; s < KT; s++) {
        if (s < KT - 1) asm volatile("cp.async.wait_group 1;");
        else            asm volatile("cp.async.wait_group 0;");
        __syncthreads();

        if (s + 2 < KT) {
            fill(s + 2);
            asm volatile("cp.async.commit_group;");
        }

        const uint32_t stg = smem_u + (uint32_t)((s % NST) * STAGE_B);
        const uint32_t aBase = stg + (uint32_t)((wm + mrow) * 128);
        const uint32_t bBase = stg + TILE_B + (uint32_t)((wn + mrow) * 128);

        #pragma unroll
        for (int ks = 0; ks < 4; ks++) {            // 4 k16-steps per stage
            const uint32_t kb = (uint32_t)((ks * 32 + klo) ^ swz);
            uint32_t af[2][4];
            ldsm_x4(af[0], aBase + kb);
            uint32_t qf[4][4];
            ldsm_x4(qf[0], bBase + 0 * 16 * 128 + kb);
            ldsm_x4(qf[1], bBase + 1 * 16 * 128 + kb);
            ldsm_x4(qf[2], bBase + 2 * 16 * 128 + kb);
            ldsm_x4(qf[3], bBase + 3 * 16 * 128 + kb);
            #pragma unroll
            for (int mt = 0; mt < 4; mt++) {
                const int cur = mt & 1;
                if (mt < 3)
                    ldsm_x4(af[cur ^ 1], aBase + (mt + 1) * 16 * 128 + kb);
                #pragma unroll
                for (int np = 0; np < 4; np++)
                    #pragma unroll
                    for (int h = 0; h < 2; h++)
                        mma16816(acc[mt][np * 2 + h], af[cur],
                                 qf[np][h], qf[np][h + 2]);
            }
        }
    }

    // ---------------- epilogues ----------------
    if (MODE == 0) {
        __nv_bfloat16* C = (__nv_bfloat16*)Cv + (size_t)bz * sCb;
        #pragma unroll
        for (int mt = 0; mt < 4; mt++)
            #pragma unroll
            for (int nt = 0; nt < 8; nt++) {
                int r   = tileM + wm + mt * 16 + g;
                int col = tileN + wn + nt * 8 + 2 * t4;
                float2 bb = *(const float2*)(bias + col);
                float2 v0 = make_float2(acc[mt][nt][0] + bb.x, acc[mt][nt][1] + bb.y);
                float2 v1 = make_float2(acc[mt][nt][2] + bb.x, acc[mt][nt][3] + bb.y);
                *(__nv_bfloat162*)(C + (size_t)r * LDC + col) =
                    __float22bfloat162_rn(v0);
                *(__nv_bfloat162*)(C + (size_t)(r + 8) * LDC + col) =
                    __float22bfloat162_rn(v1);
            }
    } else if (MODE == 1) {
        __nv_bfloat16* C = (__nv_bfloat16*)Cv + (size_t)bz * sCb;
        float cs[8][2];
        #pragma unroll
        for (int nt = 0; nt < 8; nt++) { cs[nt][0] = 0.f; cs[nt][1] = 0.f; }
        #pragma unroll
        for (int mt = 0; mt < 4; mt++)
            #pragma unroll
            for (int nt = 0; nt < 8; nt++) {
                int r0 = tileM + wm + mt * 16 + g;
                int c0 = tileN + wn + nt * 8 + 2 * t4;
                float e00 = (r0     >= c0    ) ? __expf(acc[mt][nt][0]) : 0.f;
                float e01 = (r0     >= c0 + 1) ? __expf(acc[mt][nt][1]) : 0.f;
                float e10 = (r0 + 8 >= c0    ) ? __expf(acc[mt][nt][2]) : 0.f;
                float e11 = (r0 + 8 >= c0 + 1) ? __expf(acc[mt][nt][3]) : 0.f;
                *(__nv_bfloat162*)(C + (size_t)r0 * LDC + c0) =
                    __float22bfloat162_rn(make_float2(e00, e01));
                *(__nv_bfloat162*)(C + (size_t)(r0 + 8) * LDC + c0) =
                    __float22bfloat162_rn(make_float2(e10, e11));
                cs[nt][0] += e00 + e10;
                cs[nt][1] += e01 + e11;
            }
        #pragma unroll
        for (int nt = 0; nt < 8; nt++)
            #pragma unroll
            for (int h = 0; h < 2; h++) {
                float v = cs[nt][h];
                v += __shfl_xor_sync(0xffffffffu, v, 4);
                v += __shfl_xor_sync(0xffffffffu, v, 8);
                v += __shfl_xor_sync(0xffffffffu, v, 16);
                if (lane < 4)
                    atomicAdd(psum + bz * TT + tileN + wn + nt * 8 + 2 * t4 + h, v);
            }
    } else {
        float* C = (float*)Cv + (size_t)bz * sCb;
        #pragma unroll
        for (int mt = 0; mt < 4; mt++)
            #pragma unroll
            for (int nt = 0; nt < 8; nt++) {
                int r   = tileM + wm + mt * 16 + g;
                int col = tileN + wn + nt * 8 + 2 * t4;
                float2 v0 = make_float2(acc[mt][nt][0], acc[mt][nt][1]);
                float2 v1 = make_float2(acc[mt][nt][2], acc[mt][nt][3]);
                float2 r0 = *(const float2*)(Res + (size_t)r * LDC + col);
                float2 r1 = *(const float2*)(Res + (size_t)(r + 8) * LDC + col);
                v0.x += r0.x; v0.y += r0.y;
                v1.x += r1.x; v1.y += r1.y;
                *(float2*)(C + (size_t)r * LDC + col)       = v0;
                *(float2*)(C + (size_t)(r + 8) * LDC + col) = v1;
            }
    }
}

// ---------------- merged preprocessing ----------------------------------------
// blocks [0,3072): W transpose fp32->bf16 (grid 96x32 flattened)
// blocks [3072,19456): X fp32->bf16 convert (float4 granularity)
// blocks [19456,19520): bias concat + psum zero
__global__ void k_pre(const float* __restrict__ Wq, const float* __restrict__ Wk,
                      const float* __restrict__ Wv,
                      const float* __restrict__ bq, const float* __restrict__ bk,
                      const float* __restrict__ bv,
                      const float4* __restrict__ X4,
                      __nv_bfloat16* __restrict__ Wt, float* __restrict__ biasc,
                      float* __restrict__ psum, __nv_bfloat162* __restrict__ Xb2)
{
    __shared__ float s[32][33];
    const int bx = blockIdx.x;
    const int tid = threadIdx.x;

    if (bx < 3072) {                       // ---- W transpose ----
        const int gx = bx % 96, gy = bx / 96;
        const int nb = gx * 32, kb = gy * 32;
        const float* W = (nb < 1024) ? Wq : (nb < 2048 ? Wk : Wv);
        const int nl = nb & 1023;
        const int tx = tid & 31, ty = tid >> 5;   // 32 x 8
        #pragma unroll
        for (int r = 0; r < 4; r++) {
            int k = kb + ty + r * 8;
            s[ty + r * 8][tx] = W[k * 1024 + nl + tx];
        }
        __syncthreads();
        #pragma unroll
        for (int r = 0; r < 4; r++) {
            int n = nb + ty + r * 8;
            Wt[(size_t)n * 1024 + kb + tx] = __float2bfloat16(s[tx][ty + r * 8]);
        }
    } else if (bx < 19456) {               // ---- X convert ----
        int i = (bx - 3072) * 256 + tid;   // 4194304 float4s
        float4 v = X4[i];
        Xb2[2 * i]     = __float22bfloat162_rn(make_float2(v.x, v.y));
        Xb2[2 * i + 1] = __float22bfloat162_rn(make_float2(v.z, v.w));
    } else {                               // ---- bias concat + psum zero ----
        int i = (bx - 19456) * 256 + tid;  // 16384
        psum[i] = 0.f;
        if (i < 3072)
            biasc[i] = (i < 1024) ? bq[i] : (i < 2048 ? bk[i - 1024] : bv[i - 2048]);
    }
}

// ------ transpose V slice of QKV -> Vt[b][v][t], scaled by 1/(32*psum[t]) ------
// 64x64 tiles; bf16x2 (4B) global accesses on BOTH sides (full 128B/warp).
__global__ void k_transposeVS(const __nv_bfloat16* __restrict__ QKV,
                              const float* __restrict__ psum,
                              __nv_bfloat16* __restrict__ Vt)
{
    __shared__ uint32_t s2[64][33];        // s2[t][c] = V pair {2c, 2c+1} at row t
    const int tb = blockIdx.x * 64;        // t
    const int vb = blockIdx.y * 64;        // v
    const int b  = blockIdx.z;
    const int tx = threadIdx.x, ty = threadIdx.y;   // 32 x 8

    #pragma unroll
    for (int r = 0; r < 8; r++) {
        int t = ty + r * 8;
        s2[t][tx] = *(const uint32_t*)(
            QKV + ((size_t)(b * TT + tb + t)) * 3072 + 2048 + vb + 2 * tx);
    }
    __syncthreads();

    // per-thread t-pair (2tx, 2tx+1) scales
    float iv0 = 1.0f / (psum[b * TT + tb + 2 * tx]     * 32.0f);
    float iv1 = 1.0f / (psum[b * TT + tb + 2 * tx + 1] * 32.0f);

    #pragma unroll
    for (int r = 0; r < 8; r++) {
        int v = ty + r * 8;
        uint32_t p0 = s2[2 * tx][v >> 1];
        uint32_t p1 = s2[2 * tx + 1][v >> 1];
        __nv_bfloat162 q0 = *(__nv_bfloat162*)&p0;
        __nv_bfloat162 q1 = *(__nv_bfloat162*)&p1;
        float f0 = (v & 1) ? __bfloat162float(q0.y) : __bfloat162float(q0.x);
        float f1 = (v & 1) ? __bfloat162float(q1.y) : __bfloat162float(q1.x);
        __nv_bfloat162 out = __floats2bfloat162_rn(f0 * iv0, f1 * iv1);
        *(__nv_bfloat162*)(Vt + (size_t)b * DD * TT + (size_t)(vb + v) * TT
                           + tb + 2 * tx) = out;
    }
}

// ---------------- launch --------------------------------------------------------
extern "C" void kernel_launch(void* const* d_in, const int* in_sizes, int n_in,
                              void* d_out, int out_size)
{
    (void)in_sizes; (void)n_in; (void)out_size;
    const float* X  = (const float*)d_in[0];
    const float* Wq = (const float*)d_in[1];
    const float* bq = (const float*)d_in[2];
    const float* Wk = (const float*)d_in[3];
    const float* bk = (const float*)d_in[4];
    const float* Wv = (const float*)d_in[5];
    const float* bv = (const float*)d_in[6];
    float* out = (float*)d_out;

    __nv_bfloat16 *Xb, *Wt, *QKV, *probs, *Vt;
    float *biasc, *psum;
    cudaGetSymbolAddress((void**)&Xb,    g_Xb);
    cudaGetSymbolAddress((void**)&Wt,    g_Wt);
    cudaGetSymbolAddress((void**)&biasc, g_biasc);
    cudaGetSymbolAddress((void**)&QKV,   g_QKV);
    cudaGetSymbolAddress((void**)&probs, g_probs);
    cudaGetSymbolAddress((void**)&Vt,    g_Vt);
    cudaGetSymbolAddress((void**)&psum,  g_psum);

    cudaFuncSetAttribute((const void*)gemm_bf16<0, 1024, 1024, 3072>,
                         cudaFuncAttributeMaxDynamicSharedMemorySize, SMEM_BYTES);
    cudaFuncSetAttribute((const void*)gemm_bf16<1, 3072, 3072, 2048>,
                         cudaFuncAttributeMaxDynamicSharedMemorySize, SMEM_BYTES);
    cudaFuncSetAttribute((const void*)gemm_bf16<2, 2048, 2048, 1024>,
                         cudaFuncAttributeMaxDynamicSharedMemorySize, SMEM_BYTES);

    // 1) merged preprocessing (W transpose + X convert + bias/psum)
    k_pre<<<19520, 256>>>(Wq, Wk, Wv, bq, bk, bv,
                          (const float4*)X, Wt, biasc, psum,
                          (__nv_bfloat162*)Xb);

    // 2) QKV[16384,3072] = Xb @ Wt^T + biasc  (bf16 out)
    gemm_bf16<0, 1024, 1024, 3072><<<dim3(24, 128, 1), 128, SMEM_BYTES>>>(
        Xb, Wt, QKV, biasc, nullptr, nullptr, 1024,
        0LL, 0LL, 0LL, 0LL);

    // 3) p~[b] = causal(exp(Q[b] @ K[b]^T)) bf16; column sums -> psum
    gemm_bf16<1, 3072, 3072, 2048><<<dim3(16, 16, 8), 128, SMEM_BYTES>>>(
        QKV, QKV + 1024, probs, nullptr, nullptr, psum, 1024,
        (long long)TT * 3072, (long long)TT * 3072, (long long)TT * TT, 0LL);

    // 4) V transpose + scale by 1/(32*psum) -> Vt[b][v][t]  (vectorized)
    k_transposeVS<<<dim3(32, 16, 8), dim3(32, 8)>>>(QKV, psum, Vt);

    // 5) out[b] = X[b] + p~[b] @ Vt'[b]^T  (causal-truncated K, longest-first)
    gemm_bf16<2, 2048, 2048, 1024><<<dim3(8, 16, 8), 128, SMEM_BYTES>>>(
        probs, Vt, out, nullptr, X, nullptr, 2048,
        (long long)TT * TT, (long long)DD * TT, (long long)TT * DD,
        (long long)TT * DD);
}

// round 16
// speedup vs baseline: 1.5265x; 1.0050x over previous
#include <cuda_runtime.h>
#include <cuda_bf16.h>
#include <cstdint>

// ---------------------------------------------------------------------------
// AttentionBlock: out = X + softmax_axis1(causal(Q K^T))/sqrt(k) @ V
// B=8, T=2048, D=1024. bf16 mma.sync GEMMs — R9/R14 core (2 CTA/SM, NST=3,
// BKH=64, XOR-swizzled 128B rows), compile-time leading dims.
// G2: triangular-packed grid, softmax fused into epilogue.
// G3: causal-truncated K, longest-first. Norm folded into V.
// ---------------------------------------------------------------------------

#define BATCH 8
#define TT    2048
#define DD    1024

#define BM 128
#define BN 128
#define BKH 64                          // bf16 k-elems per stage (128 B rows)
#define NST 3
#define TILE_B  16384                   // 128 rows x 128 bytes
#define STAGE_B (2 * TILE_B)            // 32768
#define SMEM_BYTES (NST * STAGE_B)      // 98304 -> 2 CTAs/SM

// ---------------- scratch (device globals; no allocation allowed) ----------
__device__ __nv_bfloat16 g_Xb[(size_t)16384 * 1024];
__device__ __nv_bfloat16 g_Wt[(size_t)3072 * 1024];        // [n][k] = W[k][n]
__device__ float         g_biasc[3072];
__device__ __nv_bfloat16 g_QKV[(size_t)16384 * 3072];      // [b*T + t][3072]
__device__ __nv_bfloat16 g_probs[(size_t)BATCH * TT * TT]; // p~ = exp(logit)
__device__ __nv_bfloat16 g_Vt[(size_t)BATCH * DD * TT];    // [b][v][t] * inv[t]
__device__ float         g_psum[BATCH * TT];

// ---------------- helpers ----------------------------------------------------
__device__ __forceinline__ void cp16(uint32_t s, const void* g) {
    asm volatile("cp.async.cg.shared.global [%0], [%1], 16;" :: "r"(s), "l"(g));
}
__device__ __forceinline__ void ldsm_x4(uint32_t* r, uint32_t saddr) {
    asm volatile("ldmatrix.sync.aligned.m8n8.x4.shared.b16 {%0,%1,%2,%3}, [%4];"
        : "=r"(r[0]), "=r"(r[1]), "=r"(r[2]), "=r"(r[3]) : "r"(saddr));
}
__device__ __forceinline__ void mma16816(float* d, const uint32_t* a,
                                         uint32_t b0, uint32_t b1) {
    asm volatile(
        "mma.sync.aligned.m16n8k16.row.col.f32.bf16.bf16.f32 "
        "{%0,%1,%2,%3},{%4,%5,%6,%7},{%8,%9},{%0,%1,%2,%3};\n"
        : "+f"(d[0]), "+f"(d[1]), "+f"(d[2]), "+f"(d[3])
        : "r"(a[0]), "r"(a[1]), "r"(a[2]), "r"(a[3]), "r"(b0), "r"(b1));
}

// ---------------- bf16 GEMM: C[m][n] = sum_k A[m][k]*B[n][k] ------------------
// CTA 128x128, 128 threads, 4 warps (2x2), warp tile 64x64, 2 CTAs/SM.
// MODE 0: out bf16 += bias[n]                              (QKV projection)
// MODE 1: out bf16 = causal(exp(acc)); column sums -> psum (logits/probs);
//         grid.x is a linear triangular index (only lower-triangle tiles).
// MODE 2: out fp32 += Res; k-loop truncated at tileM+BM; y reversed so the
//         longest tiles launch first (wave packing).                   (AV)
template<int MODE, int LDA, int LDB, int LDC>
__global__ void __launch_bounds__(128, 2)
gemm_bf16(const __nv_bfloat16* __restrict__ A, const __nv_bfloat16* __restrict__ B,
          void* __restrict__ Cv,
          const float* __restrict__ bias, const float* __restrict__ Res,
          float* __restrict__ psum, int K,
          long long sAb, long long sBb, long long sCb, long long sRb)
{
    extern __shared__ __align__(1024) char smem[];
    const int tid = threadIdx.x;
    const int bz  = blockIdx.z;

    int bym, bxn;
    if (MODE == 1) {
        // triangular decode: t -> (my, nx), nx <= my, 136 tiles for 16 rows
        int t = blockIdx.x;
        int my = (int)((sqrtf((float)(8 * t + 1)) - 1.0f) * 0.5f);
        if ((my + 1) * (my + 2) / 2 <= t) my++;
        if (my * (my + 1) / 2 > t)        my--;
        bym = my;
        bxn = t - my * (my + 1) / 2;
    } else if (MODE == 2) {
        bym = gridDim.y - 1 - blockIdx.y;   // longest tiles first
        bxn = blockIdx.x;
    } else {
        bym = blockIdx.y;
        bxn = blockIdx.x;
    }
    const int tileM = bym * BM;
    const int tileN = bxn * BN;

    A += (size_t)bz * sAb;
    B += (size_t)bz * sBb;
    if (MODE == 2) Res += (size_t)bz * sRb;

    const int wid = tid >> 5, lane = tid & 31;
    const int g = lane >> 2, t4 = lane & 3;
    const int wm = (wid >> 1) * 64;
    const int wn = (wid & 1) * 64;

    const int lj = lane >> 3, lr = lane & 7;
    const int mrow = (lj & 1) * 8 + lr;     // row within 16-row tile (&7 == lr)
    const int klo  = (lj >> 1) * 16;        // byte offset within k16 step
    const int swz  = lr * 16;               // XOR key (row&7)*16

    float acc[4][8][4];
    #pragma unroll
    for (int i = 0; i < 4; i++)
        #pragma unroll
        for (int j = 0; j < 8; j++)
            #pragma unroll
            for (int k = 0; k < 4; k++) acc[i][j][k] = 0.f;

    const uint32_t smem_u = (uint32_t)__cvta_generic_to_shared(smem);

    // fill: thread owns rows (tid>>3)+{0,16,...,112}, 16B chunk (tid&7).
    const int frow = tid >> 3, fc = tid & 7;
    const __nv_bfloat16* gA = A + (size_t)(tileM + frow) * LDA + fc * 8;
    const __nv_bfloat16* gB = B + (size_t)(tileN + frow) * LDB + fc * 8;
    const uint32_t sOff = (uint32_t)(frow * 128 + ((fc * 16) ^ ((frow & 7) * 16)));

    auto fill = [&](int s) {
        const uint32_t base = smem_u + (s % NST) * STAGE_B + sOff;
        const int kk = s * BKH;
        #pragma unroll
        for (int i = 0; i < 8; i++)
            cp16(base + i * 16 * 128, gA + (size_t)i * 16 * LDA + kk);
        #pragma unroll
        for (int i = 0; i < 8; i++)
            cp16(base + TILE_B + i * 16 * 128, gB + (size_t)i * 16 * LDB + kk);
    };

    const int Keff = (MODE == 2) ? (tileM + BM) : K;
    const int KT = Keff / BKH;                       // >= 2

    fill(0);
    asm volatile("cp.async.commit_group;");
    fill(1);
    asm volatile("cp.async.commit_group;");

    for (int s = 0; s < KT; s++) {
        if (s < KT - 1) asm volatile("cp.async.wait_group 1;");
        else            asm volatile("cp.async.wait_group 0;");
        __syncthreads();

        if (s + 2 < KT) {
            fill(s + 2);
            asm volatile("cp.async.commit_group;");
        }

        const uint32_t stg = smem_u + (uint32_t)((s % NST) * STAGE_B);
        const uint32_t aBase = stg + (uint32_t)((wm + mrow) * 128);
        const uint32_t bBase = stg + TILE_B + (uint32_t)((wn + mrow) * 128);

        #pragma unroll
        for (int ks = 0; ks < 4; ks++) {            // 4 k16-steps per stage
            const uint32_t kb = (uint32_t)((ks * 32 + klo) ^ swz);
            uint32_t af[2][4];
            ldsm_x4(af[0], aBase + kb);
            uint32_t qf[4][4];
            ldsm_x4(qf[0], bBase + 0 * 16 * 128 + kb);
            ldsm_x4(qf[1], bBase + 1 * 16 * 128 + kb);
            ldsm_x4(qf[2], bBase + 2 * 16 * 128 + kb);
            ldsm_x4(qf[3], bBase + 3 * 16 * 128 + kb);
            #pragma unroll
            for (int mt = 0; mt < 4; mt++) {
                const int cur = mt & 1;
                if (mt < 3)
                    ldsm_x4(af[cur ^ 1], aBase + (mt + 1) * 16 * 128 + kb);
                #pragma unroll
                for (int np = 0; np < 4; np++)
                    #pragma unroll
                    for (int h = 0; h < 2; h++)
                        mma16816(acc[mt][np * 2 + h], af[cur],
                                 qf[np][h], qf[np][h + 2]);
            }
        }
    }

    // ---------------- epilogues ----------------
    if (MODE == 0) {
        __nv_bfloat16* C = (__nv_bfloat16*)Cv + (size_t)bz * sCb;
        #pragma unroll
        for (int mt = 0; mt < 4; mt++)
            #pragma unroll
            for (int nt = 0; nt < 8; nt++) {
                int r   = tileM + wm + mt * 16 + g;
                int col = tileN + wn + nt * 8 + 2 * t4;
                float2 bb = *(const float2*)(bias + col);
                float2 v0 = make_float2(acc[mt][nt][0] + bb.x, acc[mt][nt][1] + bb.y);
                float2 v1 = make_float2(acc[mt][nt][2] + bb.x, acc[mt][nt][3] + bb.y);
                *(__nv_bfloat162*)(C + (size_t)r * LDC + col) =
                    __float22bfloat162_rn(v0);
                *(__nv_bfloat162*)(C + (size_t)(r + 8) * LDC + col) =
                    __float22bfloat162_rn(v1);
            }
    } else if (MODE == 1) {
        __nv_bfloat16* C = (__nv_bfloat16*)Cv + (size_t)bz * sCb;
        float cs[8][2];
        #pragma unroll
        for (int nt = 0; nt < 8; nt++) { cs[nt][0] = 0.f; cs[nt][1] = 0.f; }
        #pragma unroll
        for (int mt = 0; mt < 4; mt++)
            #pragma unroll
            for (int nt = 0; nt < 8; nt++) {
                int r0 = tileM + wm + mt * 16 + g;
                int c0 = tileN + wn + nt * 8 + 2 * t4;
                float e00 = (r0     >= c0    ) ? __expf(acc[mt][nt][0]) : 0.f;
                float e01 = (r0     >= c0 + 1) ? __expf(acc[mt][nt][1]) : 0.f;
                float e10 = (r0 + 8 >= c0    ) ? __expf(acc[mt][nt][2]) : 0.f;
                float e11 = (r0 + 8 >= c0 + 1) ? __expf(acc[mt][nt][3]) : 0.f;
                *(__nv_bfloat162*)(C + (size_t)r0 * LDC + c0) =
                    __float22bfloat162_rn(make_float2(e00, e01));
                *(__nv_bfloat162*)(C + (size_t)(r0 + 8) * LDC + c0) =
                    __float22bfloat162_rn(make_float2(e10, e11));
                cs[nt][0] += e00 + e10;
                cs[nt][1] += e01 + e11;
            }
        #pragma unroll
        for (int nt = 0; nt < 8; nt++)
            #pragma unroll
            for (int h = 0; h < 2; h++) {
                float v = cs[nt][h];
                v += __shfl_xor_sync(0xffffffffu, v, 4);
                v += __shfl_xor_sync(0xffffffffu, v, 8);
                v += __shfl_xor_sync(0xffffffffu, v, 16);
                if (lane < 4)
                    atomicAdd(psum + bz * TT + tileN + wn + nt * 8 + 2 * t4 + h, v);
            }
    } else {
        float* C = (float*)Cv + (size_t)bz * sCb;
        #pragma unroll
        for (int mt = 0; mt < 4; mt++)
            #pragma unroll
            for (int nt = 0; nt < 8; nt++) {
                int r   = tileM + wm + mt * 16 + g;
                int col = tileN + wn + nt * 8 + 2 * t4;
                float2 v0 = make_float2(acc[mt][nt][0], acc[mt][nt][1]);
                float2 v1 = make_float2(acc[mt][nt][2], acc[mt][nt][3]);
                float2 r0 = *(const float2*)(Res + (size_t)r * LDC + col);
                float2 r1 = *(const float2*)(Res + (size_t)(r + 8) * LDC + col);
                v0.x += r0.x; v0.y += r0.y;
                v1.x += r1.x; v1.y += r1.y;
                *(float2*)(C + (size_t)r * LDC + col)       = v0;
                *(float2*)(C + (size_t)(r + 8) * LDC + col) = v1;
            }
    }
}

// ---------------- merged preprocessing ----------------------------------------
// blocks [0,3072): W transpose fp32->bf16 (96x32 flattened)
// blocks [3072,11264): X fp32->bf16, 2 float4 in + 1 uint4 out per thread
// blocks [11264,11328): bias concat + psum zero
__global__ void k_pre(const float* __restrict__ Wq, const float* __restrict__ Wk,
                      const float* __restrict__ Wv,
                      const float* __restrict__ bq, const float* __restrict__ bk,
                      const float* __restrict__ bv,
                      const float4* __restrict__ X4,
                      __nv_bfloat16* __restrict__ Wt, float* __restrict__ biasc,
                      float* __restrict__ psum, uint4* __restrict__ Xb4)
{
    __shared__ float s[32][33];
    const int bx = blockIdx.x;
    const int tid = threadIdx.x;

    if (bx < 3072) {                       // ---- W transpose ----
        const int gx = bx % 96, gy = bx / 96;
        const int nb = gx * 32, kb = gy * 32;
        const float* W = (nb < 1024) ? Wq : (nb < 2048 ? Wk : Wv);
        const int nl = nb & 1023;
        const int tx = tid & 31, ty = tid >> 5;   // 32 x 8
        #pragma unroll
        for (int r = 0; r < 4; r++) {
            int k = kb + ty + r * 8;
            s[ty + r * 8][tx] = W[k * 1024 + nl + tx];
        }
        __syncthreads();
        #pragma unroll
        for (int r = 0; r < 4; r++) {
            int n = nb + ty + r * 8;
            Wt[(size_t)n * 1024 + kb + tx] = __float2bfloat16(s[tx][ty + r * 8]);
        }
    } else if (bx < 11264) {               // ---- X convert (8 floats/thread) ----
        int i = (bx - 3072) * 256 + tid;   // 2097152 uint4 outputs
        float4 a = X4[2 * i];
        float4 b = X4[2 * i + 1];
        __nv_bfloat162 p0 = __float22bfloat162_rn(make_float2(a.x, a.y));
        __nv_bfloat162 p1 = __float22bfloat162_rn(make_float2(a.z, a.w));
        __nv_bfloat162 p2 = __float22bfloat162_rn(make_float2(b.x, b.y));
        __nv_bfloat162 p3 = __float22bfloat162_rn(make_float2(b.z, b.w));
        uint4 o;
        o.x = *(uint32_t*)&p0; o.y = *(uint32_t*)&p1;
        o.z = *(uint32_t*)&p2; o.w = *(uint32_t*)&p3;
        Xb4[i] = o;
    } else {                               // ---- bias concat + psum zero ----
        int i = (bx - 11264) * 256 + tid;  // 16384
        psum[i] = 0.f;
        if (i < 3072)
            biasc[i] = (i < 1024) ? bq[i] : (i < 2048 ? bk[i - 1024] : bv[i - 2048]);
    }
}

// ------ transpose V slice of QKV -> Vt[b][v][t], scaled by 1/(32*psum[t]) ------
// 64x64 tiles; bf16x2 (4B) global accesses on BOTH sides.
__global__ void k_transposeVS(const __nv_bfloat16* __restrict__ QKV,
                              const float* __restrict__ psum,
                              __nv_bfloat16* __restrict__ Vt)
{
    __shared__ uint32_t s2[64][33];        // s2[t][c] = V pair {2c, 2c+1} at row t
    const int tb = blockIdx.x * 64;        // t
    const int vb = blockIdx.y * 64;        // v
    const int b  = blockIdx.z;
    const int tx = threadIdx.x, ty = threadIdx.y;   // 32 x 8

    #pragma unroll
    for (int r = 0; r < 8; r++) {
        int t = ty + r * 8;
        s2[t][tx] = *(const uint32_t*)(
            QKV + ((size_t)(b * TT + tb + t)) * 3072 + 2048 + vb + 2 * tx);
    }
    __syncthreads();

    float iv0 = 1.0f / (psum[b * TT + tb + 2 * tx]     * 32.0f);
    float iv1 = 1.0f / (psum[b * TT + tb + 2 * tx + 1] * 32.0f);

    #pragma unroll
    for (int r = 0; r < 8; r++) {
        int v = ty + r * 8;
        uint32_t p0 = s2[2 * tx][v >> 1];
        uint32_t p1 = s2[2 * tx + 1][v >> 1];
        __nv_bfloat162 q0 = *(__nv_bfloat162*)&p0;
        __nv_bfloat162 q1 = *(__nv_bfloat162*)&p1;
        float f0 = (v & 1) ? __bfloat162float(q0.y) : __bfloat162float(q0.x);
        float f1 = (v & 1) ? __bfloat162float(q1.y) : __bfloat162float(q1.x);
        __nv_bfloat162 out = __floats2bfloat162_rn(f0 * iv0, f1 * iv1);
        *(__nv_bfloat162*)(Vt + (size_t)b * DD * TT + (size_t)(vb + v) * TT
                           + tb + 2 * tx) = out;
    }
}

// ---------------- launch --------------------------------------------------------
extern "C" void kernel_launch(void* const* d_in, const int* in_sizes, int n_in,
                              void* d_out, int out_size)
{
    (void)in_sizes; (void)n_in; (void)out_size;
    const float* X  = (const float*)d_in[0];
    const float* Wq = (const float*)d_in[1];
    const float* bq = (const float*)d_in[2];
    const float* Wk = (const float*)d_in[3];
    const float* bk = (const float*)d_in[4];
    const float* Wv = (const float*)d_in[5];
    const float* bv = (const float*)d_in[6];
    float* out = (float*)d_out;

    __nv_bfloat16 *Xb, *Wt, *QKV, *probs, *Vt;
    float *biasc, *psum;
    cudaGetSymbolAddress((void**)&Xb,    g_Xb);
    cudaGetSymbolAddress((void**)&Wt,    g_Wt);
    cudaGetSymbolAddress((void**)&biasc, g_biasc);
    cudaGetSymbolAddress((void**)&QKV,   g_QKV);
    cudaGetSymbolAddress((void**)&probs, g_probs);
    cudaGetSymbolAddress((void**)&Vt,    g_Vt);
    cudaGetSymbolAddress((void**)&psum,  g_psum);

    cudaFuncSetAttribute((const void*)gemm_bf16<0, 1024, 1024, 3072>,
                         cudaFuncAttributeMaxDynamicSharedMemorySize, SMEM_BYTES);
    cudaFuncSetAttribute((const void*)gemm_bf16<1, 3072, 3072, 2048>,
                         cudaFuncAttributeMaxDynamicSharedMemorySize, SMEM_BYTES);
    cudaFuncSetAttribute((const void*)gemm_bf16<2, 2048, 2048, 1024>,
                         cudaFuncAttributeMaxDynamicSharedMemorySize, SMEM_BYTES);

    // 1) merged preprocessing (W transpose + X convert + bias/psum)
    k_pre<<<11328, 256>>>(Wq, Wk, Wv, bq, bk, bv,
                          (const float4*)X, Wt, biasc, psum, (uint4*)Xb);

    // 2) QKV[16384,3072] = Xb @ Wt^T + biasc  (bf16 out)
    gemm_bf16<0, 1024, 1024, 3072><<<dim3(24, 128, 1), 128, SMEM_BYTES>>>(
        Xb, Wt, QKV, biasc, nullptr, nullptr, 1024,
        0LL, 0LL, 0LL, 0LL);

    // 3) p~[b] = causal(exp(Q[b] @ K[b]^T)) bf16; column sums -> psum
    //    triangular-packed grid: 136 lower-triangle tiles per batch
    gemm_bf16<1, 3072, 3072, 2048><<<dim3(136, 1, 8), 128, SMEM_BYTES>>>(
        QKV, QKV + 1024, probs, nullptr, nullptr, psum, 1024,
        (long long)TT * 3072, (long long)TT * 3072, (long long)TT * TT, 0LL);

    // 4) V transpose + scale by 1/(32*psum) -> Vt[b][v][t]  (vectorized)
    k_transposeVS<<<dim3(32, 16, 8), dim3(32, 8)>>>(QKV, psum, Vt);

    // 5) out[b] = X[b] + p~[b] @ Vt'[b]^T  (causal-truncated K, longest-first)
    gemm_bf16<2, 2048, 2048, 1024><<<dim3(8, 16, 8), 128, SMEM_BYTES>>>(
        probs, Vt, out, nullptr, X, nullptr, 2048,
        (long long)TT * TT, (long long)DD * TT, (long long)TT * DD,
        (long long)TT * DD);
}